// round 8
// baseline (speedup 1.0000x reference)
#include <cuda_runtime.h>
#include <cuda_bf16.h>
#include <cstdint>
#include <cstddef>

// ---------------------------------------------------------------------------
// Problem dims (fixed)
// ---------------------------------------------------------------------------
#define BATCH   4
#define SEQ     2048
#define TOK     (BATCH * SEQ)      // 8192
#define DMODEL  384
#define INNER   768
#define STATE   16
#define KW      4
#define FFN     1024

// scan chunking
#define CH      16                 // chunks per sequence
#define CT      (SEQ / CH)         // 128 steps per chunk

// ---------------------------------------------------------------------------
// Scratch (device globals; no allocation allowed)
// ---------------------------------------------------------------------------
__device__ float g_h   [TOK * DMODEL];        // rms1 out
__device__ float g_xz  [TOK * 2 * INNER];     // in_proj out (x_inner | z)
__device__ float g_xs  [TOK * KW * INNER];    // im2col shifted input for conv
__device__ float g_xc  [TOK * INNER];         // conv out (silu)
__device__ float g_bc  [TOK * 2 * STATE];     // x_proj out (B | C)
__device__ float g_dl  [TOK * INNER];         // dsp = softplus(delta)
__device__ float g_y   [TOK * INNER];         // gated scan output
__device__ float g_o   [TOK * DMODEL];        // out_proj result
__device__ float g_x2  [TOK * DMODEL];        // residual after mamba
__device__ float g_h2  [TOK * DMODEL];        // rms2 out
__device__ float g_gate[TOK * FFN];
__device__ float g_hid [TOK * FFN];
__device__ float g_pa  [BATCH * CH * INNER * STATE];  // chunk propagator
__device__ float g_he  [BATCH * CH * INNER * STATE];  // chunk end state (local)
__device__ float g_hin [BATCH * CH * INNER * STATE];  // state entering chunk

// ---------------------------------------------------------------------------
// TF32 tensor-core GEMM: C[M,N] = A[M,K] @ B[K,N], row-major.
// CTA tile 128x128, BK=16 double-buffered, 8 warps each 32(M)x64(N).
// Fragment-vectorized smem: A as uint4 {(m,k),(m+8,k),(m,k+4),(m+8,k+4)},
// B as uint2 {(k,n),(k+4,n)} -> 2x LDS.128 + 8x LDS.64 per k8 step
// (was 24x LDS.32). XOR slot swizzle keeps every phase conflict-free.
// mode: 0 = store, 1 = silu(acc+bias), 2 = acc+bias, 3 = acc+res,
//       4 = softplus(acc+bias), 5 = silu(res)*acc
// ---------------------------------------------------------------------------
#define BM 128
#define BN 128
#define BKT 16

__device__ __forceinline__ uint32_t f2tf(float f)
{
    uint32_t u;
    asm("cvt.rna.tf32.f32 %0, %1;" : "=r"(u) : "f"(f));
    return u;
}

__device__ __forceinline__ void mma_tf32(float c[4], const uint32_t a[4],
                                         const uint32_t b[2])
{
    asm volatile(
        "mma.sync.aligned.m16n8k8.row.col.f32.tf32.tf32.f32 "
        "{%0,%1,%2,%3}, {%4,%5,%6,%7}, {%8,%9}, {%0,%1,%2,%3};\n"
        : "+f"(c[0]), "+f"(c[1]), "+f"(c[2]), "+f"(c[3])
        : "r"(a[0]), "r"(a[1]), "r"(a[2]), "r"(a[3]),
          "r"(b[0]), "r"(b[1]));
}

__device__ __forceinline__ float epi_apply(float v, int mode, int n, int N,
                                           int m, const float* bias,
                                           const float* res)
{
    if (mode == 1) {
        v += bias[n];
        v = v / (1.f + __expf(-v));
    } else if (mode == 2) {
        v += bias[n];
    } else if (mode == 3) {
        v += res[(size_t)m * N + n];
    } else if (mode == 4) {
        v += bias[n];
        v = (v > 20.f) ? v : log1pf(__expf(v));
    } else if (mode == 5) {
        const float gv = res[(size_t)m * N + n];
        v *= gv / (1.f + __expf(-gv));
    }
    return v;
}

__global__ __launch_bounds__(256, 2) void mma_gemm_kernel(
    const float* __restrict__ A, const float* __restrict__ B,
    float* __restrict__ C, int M, int N, int K,
    int mode, const float* __restrict__ bias, const float* __restrict__ res)
{
    // A: [64 mrow][8 slot] uint4 ; B: [128 n][8 slot] uint2  (per buffer)
    __shared__ uint4 AsV[2][64][8];
    __shared__ uint2 BsV[2][128][8];

    const int tid  = threadIdx.x;
    const int wid  = tid >> 5;
    const int lane = tid & 31;
    const int g    = lane >> 2;   // 0..7
    const int tig  = lane & 3;    // 0..3

    const int warpM = (wid & 3) * 32;
    const int warpN = (wid >> 2) * 64;

    const int m0 = blockIdx.y * BM;
    const int n0 = blockIdx.x * BN;

    const int ar = tid >> 2;          // 0..63  (rows ar, ar+64)
    const int ac = (tid & 3) * 4;     // 0,4,8,12
    const int br = tid >> 5;          // 0..7   (rows br, br+8)
    const int bcn = (tid & 31) * 4;   // 0..124

    float acc[2][8][4];
    #pragma unroll
    for (int mt = 0; mt < 2; mt++)
        #pragma unroll
        for (int nt = 0; nt < 8; nt++)
            #pragma unroll
            for (int r = 0; r < 4; r++) acc[mt][nt][r] = 0.f;

    const bool bok = (n0 + bcn + 3) < N;
    const float4 zero4 = make_float4(0.f, 0.f, 0.f, 0.f);

    const float* Ab = A + (size_t)(m0 + ar) * K + ac;
    const float* Bb = B + (size_t)br * N + n0 + bcn;

    float4 av0, av1, bv0, bv1;

    av0 = *(const float4*)(Ab);
    av1 = *(const float4*)(Ab + (size_t)64 * K);
    bv0 = bok ? *(const float4*)(Bb) : zero4;
    bv1 = bok ? *(const float4*)(Bb + (size_t)8 * N) : zero4;

    const int ntiles = K / BKT;
    int buf = 0;

    // smem store helpers (tile-local coords: m in 0..127, k in 0..15, n in 0..127)
    auto stA = [&](int bufi, int m, int k, float val) {
        const int mrow  = ((m >> 4) << 3) | (m & 7);
        const int hi    = (m >> 3) & 1;
        const int ks2   = k >> 3;
        const int kk    = k & 3;
        const int khalf = (k >> 2) & 1;
        const int slot  = ((ks2 << 2) | kk) ^ ((mrow & 1) << 2);
        ((uint32_t*)&AsV[bufi][mrow][slot])[hi + (khalf << 1)] = f2tf(val);
    };
    auto stB = [&](int bufi, int k, int n, float val) {
        const int ks2   = k >> 3;
        const int kk    = k & 3;
        const int khalf = (k >> 2) & 1;
        const int slot  = ((ks2 << 2) | kk) ^ (((n >> 1) & 1) << 2);
        ((uint32_t*)&BsV[bufi][n][slot])[khalf] = f2tf(val);
    };
    auto store_tile = [&](int bufi, const float4& a0, const float4& a1,
                          const float4& b0, const float4& b1) {
        stA(bufi, ar,      ac + 0, a0.x);
        stA(bufi, ar,      ac + 1, a0.y);
        stA(bufi, ar,      ac + 2, a0.z);
        stA(bufi, ar,      ac + 3, a0.w);
        stA(bufi, ar + 64, ac + 0, a1.x);
        stA(bufi, ar + 64, ac + 1, a1.y);
        stA(bufi, ar + 64, ac + 2, a1.z);
        stA(bufi, ar + 64, ac + 3, a1.w);
        stB(bufi, br,     bcn + 0, b0.x);
        stB(bufi, br,     bcn + 1, b0.y);
        stB(bufi, br,     bcn + 2, b0.z);
        stB(bufi, br,     bcn + 3, b0.w);
        stB(bufi, br + 8, bcn + 0, b1.x);
        stB(bufi, br + 8, bcn + 1, b1.y);
        stB(bufi, br + 8, bcn + 2, b1.z);
        stB(bufi, br + 8, bcn + 3, b1.w);
    };

    store_tile(0, av0, av1, bv0, bv1);
    __syncthreads();

    const int mrow0 = ((warpM >> 4) << 3) + g;       // mt=0 row in AsV
    const int aswz  = (g & 1) << 2;
    const int bswz  = ((g >> 1) & 1) << 2;

    for (int t = 0; t < ntiles; t++) {
        if (t + 1 < ntiles) {
            const int k0 = (t + 1) * BKT;
            av0 = *(const float4*)(Ab + k0);
            av1 = *(const float4*)(Ab + k0 + (size_t)64 * K);
            bv0 = bok ? *(const float4*)(Bb + (size_t)k0 * N) : zero4;
            bv1 = bok ? *(const float4*)(Bb + (size_t)(k0 + 8) * N) : zero4;
        }

        #pragma unroll
        for (int ks2 = 0; ks2 < 2; ks2++) {
            const int sbase = (ks2 << 2) | tig;
            const int aslot = sbase ^ aswz;
            const int bslot = sbase ^ bswz;

            uint32_t afr[2][4];
            #pragma unroll
            for (int mt = 0; mt < 2; mt++) {
                const uint4 va = AsV[buf][mrow0 + (mt << 3)][aslot];
                afr[mt][0] = va.x; afr[mt][1] = va.y;
                afr[mt][2] = va.z; afr[mt][3] = va.w;
            }
            uint32_t bfr[8][2];
            #pragma unroll
            for (int nt = 0; nt < 8; nt++) {
                const uint2 vb = BsV[buf][warpN + (nt << 3) + g][bslot];
                bfr[nt][0] = vb.x; bfr[nt][1] = vb.y;
            }
            #pragma unroll
            for (int mt = 0; mt < 2; mt++)
                #pragma unroll
                for (int nt = 0; nt < 8; nt++)
                    mma_tf32(acc[mt][nt], afr[mt], bfr[nt]);
        }

        if (t + 1 < ntiles) {
            const int nb = buf ^ 1;
            store_tile(nb, av0, av1, bv0, bv1);
            __syncthreads();
            buf = nb;
        }
    }

    #pragma unroll
    for (int mt = 0; mt < 2; mt++) {
        #pragma unroll
        for (int nt = 0; nt < 8; nt++) {
            const int mA = m0 + warpM + mt * 16 + g;
            const int mB = mA + 8;
            const int n  = n0 + warpN + nt * 8 + tig * 2;
            #pragma unroll
            for (int half = 0; half < 2; half++) {
                const int m = half ? mB : mA;
                float v0 = half ? acc[mt][nt][2] : acc[mt][nt][0];
                float v1 = half ? acc[mt][nt][3] : acc[mt][nt][1];
                if (n < N) {
                    v0 = epi_apply(v0, mode, n, N, m, bias, res);
                    C[(size_t)m * N + n] = v0;
                }
                if (n + 1 < N) {
                    v1 = epi_apply(v1, mode, n + 1, N, m, bias, res);
                    C[(size_t)m * N + n + 1] = v1;
                }
            }
        }
    }
}

// ---------------------------------------------------------------------------
// RMSNorm (warp per token, D=384 -> 12 elems/lane)
// ---------------------------------------------------------------------------
__global__ void rmsnorm_kernel(const float* __restrict__ x,
                               const float* __restrict__ w,
                               float* __restrict__ out)
{
    const int warp = (blockIdx.x * blockDim.x + threadIdx.x) >> 5;
    const int lane = threadIdx.x & 31;
    if (warp >= TOK) return;
    const float* row = x + (size_t)warp * DMODEL;
    float ss = 0.f;
    float v[12];
    #pragma unroll
    for (int c = 0; c < 12; c++) {
        v[c] = row[lane + c * 32];
        ss += v[c] * v[c];
    }
    #pragma unroll
    for (int o = 16; o; o >>= 1) ss += __shfl_xor_sync(0xffffffffu, ss, o);
    const float inv = rsqrtf(ss * (1.f / DMODEL) + 1e-6f);
    float* orow = out + (size_t)warp * DMODEL;
    #pragma unroll
    for (int c = 0; c < 12; c++) {
        const int i = lane + c * 32;
        orow[i] = v[c] * inv * w[i];
    }
}

// ---------------------------------------------------------------------------
// im2col for conv: xs[tok, w*INNER + i] = x_inner[b, t-1+w, i] (0 outside seq)
// ---------------------------------------------------------------------------
__global__ void conv_shift_kernel(const float* __restrict__ xz,
                                  float* __restrict__ xs)
{
    const int idx = blockIdx.x * blockDim.x + threadIdx.x;   // float4 id
    const int total = TOK * KW * INNER / 4;
    if (idx >= total) return;
    const int e = idx * 4;
    const int tok = e / (KW * INNER);
    const int c = e - tok * (KW * INNER);
    const int w = c / INNER;
    const int i = c - w * INNER;
    const int b = tok >> 11;
    const int t = tok & (SEQ - 1);
    const int ts = t - 1 + w;
    float4 v = make_float4(0.f, 0.f, 0.f, 0.f);
    if (ts >= 0 && ts < SEQ)
        v = *(const float4*)(xz + ((size_t)(b * SEQ + ts)) * (2 * INNER) + i);
    *(float4*)(xs + (size_t)e) = v;
}

// ---------------------------------------------------------------------------
// Chunked selective scan.
// Phase 1: per (b, chunk, d, n): local scan with h_in = 0.
// ---------------------------------------------------------------------------
__global__ void scan_chunk_kernel(const float* __restrict__ xc,
                                  const float* __restrict__ dsp_,
                                  const float* __restrict__ bc,
                                  const float* __restrict__ A_log,
                                  const float* __restrict__ Dp,
                                  float* __restrict__ yloc,
                                  float* __restrict__ pa,
                                  float* __restrict__ he)
{
    const int idx = blockIdx.x * blockDim.x + threadIdx.x;
    const int n = idx & 15;
    const int grp = idx >> 4;              // (b*CH + c)*INNER + d
    const int d = grp % INNER;
    const int bch = grp / INNER;           // b*CH + c
    const int c = bch & (CH - 1);
    const int b = bch >> 4;                // CH == 16

    const float A = -__expf(A_log[d * STATE + n]);
    const float Dv = Dp[d];
    float S = 0.f, s = 0.f;

    size_t tok = (size_t)b * SEQ + (size_t)c * CT;

    float dsp = dsp_[tok * INNER + d];
    float xv  = xc[tok * INNER + d];
    float Bv  = bc[tok * 2 * STATE + n];
    float Cv  = bc[tok * 2 * STATE + STATE + n];

    for (int t = 0; t < CT; t++) {
        float dsp_nx = 0.f, x_nx = 0.f, b_nx = 0.f, c_nx = 0.f;
        if (t + 1 < CT) {
            const size_t tk = tok + 1;
            dsp_nx = dsp_[tk * INNER + d];
            x_nx   = xc[tk * INNER + d];
            b_nx   = bc[tk * 2 * STATE + n];
            c_nx   = bc[tk * 2 * STATE + STATE + n];
        }
        S += dsp;
        const float a = __expf(A * dsp);
        s = a * s + dsp * Bv * xv;
        float p = Cv * s;
        p += __shfl_xor_sync(0xffffffffu, p, 8);
        p += __shfl_xor_sync(0xffffffffu, p, 4);
        p += __shfl_xor_sync(0xffffffffu, p, 2);
        p += __shfl_xor_sync(0xffffffffu, p, 1);
        if (n == 0)
            yloc[tok * INNER + d] = p + Dv * xv;
        tok++;
        dsp = dsp_nx; xv = x_nx; Bv = b_nx; Cv = c_nx;
    }

    const size_t o = (size_t)grp * STATE + n;
    pa[o] = __expf(A * S);
    he[o] = s;
}

// ---------------------------------------------------------------------------
// Phase 2: sequential combine over chunks. thread per (b, d, n).
// ---------------------------------------------------------------------------
__global__ void scan_combine_kernel(const float* __restrict__ pa,
                                    const float* __restrict__ he,
                                    float* __restrict__ hin)
{
    const int idx = blockIdx.x * blockDim.x + threadIdx.x;
    if (idx >= BATCH * INNER * STATE) return;
    const int n = idx & 15;
    const int grp = idx >> 4;              // b*INNER + d
    const int d = grp % INNER;
    const int b = grp / INNER;

    float h = 0.f;
    #pragma unroll
    for (int c = 0; c < CH; c++) {
        const size_t o = (((size_t)(b * CH + c) * INNER) + d) * STATE + n;
        hin[o] = h;
        h = pa[o] * h + he[o];
    }
}

// ---------------------------------------------------------------------------
// Phase 3: add cross-chunk correction, apply silu(z) gate.
// ---------------------------------------------------------------------------
__global__ void scan_fixup_kernel(const float* __restrict__ dsp_,
                                  const float* __restrict__ bc,
                                  const float* __restrict__ A_log,
                                  const float* __restrict__ hin,
                                  const float* __restrict__ yloc,
                                  const float* __restrict__ xz,
                                  float* __restrict__ y)
{
    const int idx = blockIdx.x * blockDim.x + threadIdx.x;
    const int n = idx & 15;
    const int grp = idx >> 4;              // (b*CH + c)*INNER + d
    const int d = grp % INNER;
    const int bch = grp / INNER;
    const int c = bch & (CH - 1);
    const int b = bch >> 4;

    const float A = -__expf(A_log[d * STATE + n]);
    const float h0 = hin[(size_t)grp * STATE + n];
    float S = 0.f;

    size_t tok = (size_t)b * SEQ + (size_t)c * CT;

    float dsp = dsp_[tok * INNER + d];
    float Cv  = bc[tok * 2 * STATE + STATE + n];

    for (int t = 0; t < CT; t++) {
        float dsp_nx = 0.f, c_nx = 0.f;
        if (t + 1 < CT) {
            const size_t tk = tok + 1;
            dsp_nx = dsp_[tk * INNER + d];
            c_nx   = bc[tk * 2 * STATE + STATE + n];
        }
        S += dsp;
        float p = Cv * __expf(A * S) * h0;
        p += __shfl_xor_sync(0xffffffffu, p, 8);
        p += __shfl_xor_sync(0xffffffffu, p, 4);
        p += __shfl_xor_sync(0xffffffffu, p, 2);
        p += __shfl_xor_sync(0xffffffffu, p, 1);
        if (n == 0) {
            const float zv = xz[tok * 2 * INNER + INNER + d];
            const float sz = zv / (1.f + __expf(-zv));
            y[tok * INNER + d] = (yloc[tok * INNER + d] + p) * sz;
        }
        tok++;
        dsp = dsp_nx; Cv = c_nx;
    }
}

// ---------------------------------------------------------------------------
// Fused: x2 = xres + LayerNorm(o)*gamma+beta ; h2 = RMSNorm(x2)*rms_w
// ---------------------------------------------------------------------------
__global__ void ln_residual_rms_kernel(const float* __restrict__ o_,
                                       const float* __restrict__ xres,
                                       const float* __restrict__ gamma,
                                       const float* __restrict__ beta,
                                       const float* __restrict__ rms_w,
                                       float* __restrict__ x2,
                                       float* __restrict__ h2)
{
    const int warp = (blockIdx.x * blockDim.x + threadIdx.x) >> 5;
    const int lane = threadIdx.x & 31;
    if (warp >= TOK) return;
    const size_t row = (size_t)warp * DMODEL;

    float o[12];
    float mu = 0.f;
    #pragma unroll
    for (int c = 0; c < 12; c++) {
        o[c] = o_[row + lane + c * 32];
        mu += o[c];
    }
    #pragma unroll
    for (int s = 16; s; s >>= 1) mu += __shfl_xor_sync(0xffffffffu, mu, s);
    mu *= (1.f / DMODEL);

    float var = 0.f;
    #pragma unroll
    for (int c = 0; c < 12; c++) {
        const float dd = o[c] - mu;
        var += dd * dd;
    }
    #pragma unroll
    for (int s = 16; s; s >>= 1) var += __shfl_xor_sync(0xffffffffu, var, s);
    var *= (1.f / DMODEL);
    const float inv = rsqrtf(var + 1e-5f);

    float r[12];
    float ss = 0.f;
    #pragma unroll
    for (int c = 0; c < 12; c++) {
        const int i = lane + c * 32;
        const float v = xres[row + i] + (o[c] - mu) * inv * gamma[i] + beta[i];
        r[c] = v;
        x2[row + i] = v;
        ss += v * v;
    }
    #pragma unroll
    for (int s = 16; s; s >>= 1) ss += __shfl_xor_sync(0xffffffffu, ss, s);
    const float rinv = rsqrtf(ss * (1.f / DMODEL) + 1e-6f);
    #pragma unroll
    for (int c = 0; c < 12; c++) {
        const int i = lane + c * 32;
        h2[row + i] = r[c] * rinv * rms_w[i];
    }
}

// ---------------------------------------------------------------------------
// launch
// ---------------------------------------------------------------------------
static inline float* sym(const void* symbol)
{
    void* p = nullptr;
    cudaGetSymbolAddress(&p, symbol);
    return (float*)p;
}

extern "C" void kernel_launch(void* const* d_in, const int* in_sizes, int n_in,
                              void* d_out, int out_size)
{
    const float* x        = (const float*)d_in[0];
    const float* rms1_w   = (const float*)d_in[1];
    const float* rms2_w   = (const float*)d_in[2];
    const float* in_proj  = (const float*)d_in[3];
    const float* conv_w   = (const float*)d_in[4];
    const float* conv_b   = (const float*)d_in[5];
    const float* x_proj   = (const float*)d_in[6];
    const float* dt_proj  = (const float*)d_in[7];
    const float* dt_b     = (const float*)d_in[8];
    const float* A_log    = (const float*)d_in[9];
    const float* D_param  = (const float*)d_in[10];
    const float* out_proj = (const float*)d_in[11];
    const float* ln_g     = (const float*)d_in[12];
    const float* ln_b     = (const float*)d_in[13];
    const float* gate_w   = (const float*)d_in[14];
    const float* up_w     = (const float*)d_in[15];
    const float* down_w   = (const float*)d_in[16];
    float* out = (float*)d_out;

    float* h    = sym(g_h);
    float* xz   = sym(g_xz);
    float* xs   = sym(g_xs);
    float* xc   = sym(g_xc);
    float* bcp  = sym(g_bc);
    float* dl   = sym(g_dl);
    float* y    = sym(g_y);
    float* o    = sym(g_o);
    float* x2   = sym(g_x2);
    float* h2   = sym(g_h2);
    float* gate = sym(g_gate);
    float* hid  = sym(g_hid);
    float* pa   = sym(g_pa);
    float* he   = sym(g_he);
    float* hin  = sym(g_hin);

    const dim3 tpb(256);

    // 1. h = rmsnorm(x) * rms1_w
    rmsnorm_kernel<<<TOK / 8, 256>>>(x, rms1_w, h);

    // 2. xz = h @ in_proj_w   [8192,1536] K=384
    mma_gemm_kernel<<<dim3((2 * INNER) / BN, TOK / BM), tpb>>>(
        h, in_proj, xz, TOK, 2 * INNER, DMODEL, 0, nullptr, nullptr);

    // 3. im2col shift
    {
        const int total = TOK * KW * INNER / 4;
        conv_shift_kernel<<<(total + 255) / 256, tpb>>>(xz, xs);
    }

    // 4. xc = silu(xs @ conv_w_reshaped + conv_b)   K=3072
    mma_gemm_kernel<<<dim3(INNER / BN, TOK / BM), tpb>>>(
        xs, conv_w, xc, TOK, INNER, KW * INNER, 1, conv_b, nullptr);

    // 5. bc = xc @ x_proj_w   [8192,32]  K=768
    mma_gemm_kernel<<<dim3(1, TOK / BM), tpb>>>(
        xc, x_proj, bcp, TOK, 2 * STATE, INNER, 0, nullptr, nullptr);

    // 6. dsp = softplus(xc @ dt_proj_w + dt_b)   K=768
    mma_gemm_kernel<<<dim3(INNER / BN, TOK / BM), tpb>>>(
        xc, dt_proj, dl, TOK, INNER, INNER, 4, dt_b, nullptr);

    // 7. chunked selective scan + gating
    scan_chunk_kernel<<<(BATCH * CH * INNER * STATE) / 256, tpb>>>(
        xc, dl, bcp, A_log, D_param, y, pa, he);
    scan_combine_kernel<<<(BATCH * INNER * STATE + 255) / 256, tpb>>>(
        pa, he, hin);
    scan_fixup_kernel<<<(BATCH * CH * INNER * STATE) / 256, tpb>>>(
        dl, bcp, A_log, hin, y, xz, y);

    // 8. o = y @ out_proj_w   [8192,384] K=768
    mma_gemm_kernel<<<dim3(DMODEL / BN, TOK / BM), tpb>>>(
        y, out_proj, o, TOK, DMODEL, INNER, 0, nullptr, nullptr);

    // 9. x2 = x + LN(o); h2 = RMSNorm(x2)
    ln_residual_rms_kernel<<<TOK / 8, 256>>>(o, x, ln_g, ln_b, rms2_w, x2, h2);

    // 10. gate GEMM  K=384
    mma_gemm_kernel<<<dim3(FFN / BN, TOK / BM), tpb>>>(
        h2, gate_w, gate, TOK, FFN, DMODEL, 0, nullptr, nullptr);
    // 11. hid = silu(gate) * (h2 @ up_w)   (fused)
    mma_gemm_kernel<<<dim3(FFN / BN, TOK / BM), tpb>>>(
        h2, up_w, hid, TOK, FFN, DMODEL, 5, nullptr, gate);

    // 12. out = x2 + hid @ down_w   K=1024
    mma_gemm_kernel<<<dim3(DMODEL / BN, TOK / BM), tpb>>>(
        hid, down_w, out, TOK, DMODEL, FFN, 3, nullptr, x2);
}

// round 10
// speedup vs baseline: 1.2008x; 1.2008x over previous
#include <cuda_runtime.h>
#include <cuda_bf16.h>
#include <cstdint>
#include <cstddef>

// ---------------------------------------------------------------------------
// Problem dims (fixed)
// ---------------------------------------------------------------------------
#define BATCH   4
#define SEQ     2048
#define TOK     (BATCH * SEQ)      // 8192
#define DMODEL  384
#define INNER   768
#define STATE   16
#define KW      4
#define FFN     1024

// scan chunking
#define CH      16                 // chunks per sequence
#define CT      (SEQ / CH)         // 128 steps per chunk

// ---------------------------------------------------------------------------
// Scratch (device globals; no allocation allowed)
// ---------------------------------------------------------------------------
__device__ float g_h   [TOK * DMODEL];        // rms1 out
__device__ float g_xz  [TOK * 2 * INNER];     // in_proj out (x_inner | z)
__device__ float g_xc  [TOK * INNER];         // conv out (silu)
__device__ float g_bc  [TOK * 2 * STATE];     // x_proj out (B | C)
__device__ float g_dl  [TOK * INNER];         // dsp = softplus(delta)
__device__ float g_y   [TOK * INNER];         // gated scan output
__device__ float g_o   [TOK * DMODEL];        // out_proj result
__device__ float g_x2  [TOK * DMODEL];        // residual after mamba
__device__ float g_h2  [TOK * DMODEL];        // rms2 out
__device__ float g_gate[TOK * FFN];
__device__ float g_hid [TOK * FFN];
__device__ float g_pa  [BATCH * CH * INNER * STATE];  // chunk propagator
__device__ float g_he  [BATCH * CH * INNER * STATE];  // chunk end state (local)
__device__ float g_hin [BATCH * CH * INNER * STATE];  // state entering chunk

// ---------------------------------------------------------------------------
// TF32 tensor-core GEMM: C[M,N] = A[M,K] @ B[K,N], row-major.
// CTA tile 128x128, BK=16 double-buffered, 8 warps each 32(M)x64(N),
// mma.sync.aligned.m16n8k8.row.col.f32.tf32.tf32.f32
// Requirements: M % 128 == 0, K % 16 == 0, N % 4 == 0 (guards on N only).
// mode: 0 = store, 1 = silu(acc+bias), 2 = acc+bias, 3 = acc + res[m*N+n],
//       4 = softplus(acc+bias), 5 = silu(res)*acc
// amode: 0 = A is row-major [M,K] dense
//        1 = A is the conv im2col view of xz: logical col k -> tap w = k/768,
//            chan i = k%768; A[m][k] = xz[(b, t-1+w)][i], 0 outside sequence.
// ---------------------------------------------------------------------------
#define BM 128
#define BN 128
#define BKT 16
#define LDA (BM + 4)
#define LDB (BN + 4)

__device__ __forceinline__ uint32_t f2tf(float f)
{
    uint32_t u;
    asm("cvt.rna.tf32.f32 %0, %1;" : "=r"(u) : "f"(f));
    return u;
}

__device__ __forceinline__ void mma_tf32(float c[4], const uint32_t a[4],
                                         const uint32_t b[2])
{
    asm volatile(
        "mma.sync.aligned.m16n8k8.row.col.f32.tf32.tf32.f32 "
        "{%0,%1,%2,%3}, {%4,%5,%6,%7}, {%8,%9}, {%0,%1,%2,%3};\n"
        : "+f"(c[0]), "+f"(c[1]), "+f"(c[2]), "+f"(c[3])
        : "r"(a[0]), "r"(a[1]), "r"(a[2]), "r"(a[3]),
          "r"(b[0]), "r"(b[1]));
}

__device__ __forceinline__ float epi_apply(float v, int mode, int n, int N,
                                           int m, const float* bias,
                                           const float* res)
{
    if (mode == 1) {
        v += bias[n];
        v = v / (1.f + __expf(-v));
    } else if (mode == 2) {
        v += bias[n];
    } else if (mode == 3) {
        v += res[(size_t)m * N + n];
    } else if (mode == 4) {
        v += bias[n];
        v = (v > 20.f) ? v : log1pf(__expf(v));
    } else if (mode == 5) {
        const float gv = res[(size_t)m * N + n];
        v *= gv / (1.f + __expf(-gv));
    }
    return v;
}

// load one A float4 for (row m0+ar of the GEMM, cols k..k+3)
__device__ __forceinline__ float4 load_a4(const float* __restrict__ A,
                                          int arow, int k, int K, int amode)
{
    if (amode == 0) {
        return *(const float4*)(A + (size_t)arow * K + k);
    }
    // conv view: A base is xz (row stride 2*INNER), first INNER cols = x_inner
    const int w = k / INNER;
    const int i = k - w * INNER;
    const int t = arow & (SEQ - 1);
    const int ts = t - 1 + w;
    if (ts < 0 || ts >= SEQ)
        return make_float4(0.f, 0.f, 0.f, 0.f);
    const int brow = (arow & ~(SEQ - 1)) + ts;     // same batch, shifted time
    return *(const float4*)(A + (size_t)brow * (2 * INNER) + i);
}

__global__ __launch_bounds__(256, 2) void mma_gemm_kernel(
    const float* __restrict__ A, const float* __restrict__ B,
    float* __restrict__ C, int M, int N, int K,
    int mode, const float* __restrict__ bias, const float* __restrict__ res,
    int amode)
{
    __shared__ uint32_t As[2][BKT][LDA];
    __shared__ uint32_t Bs[2][BKT][LDB];

    const int tid  = threadIdx.x;
    const int wid  = tid >> 5;
    const int lane = tid & 31;
    const int g    = lane >> 2;   // 0..7
    const int tig  = lane & 3;    // 0..3

    const int warpM = (wid & 3) * 32;
    const int warpN = (wid >> 2) * 64;

    const int m0 = blockIdx.y * BM;
    const int n0 = blockIdx.x * BN;

    const int ar = tid >> 2;          // 0..63  (rows ar, ar+64)
    const int ac = (tid & 3) * 4;     // 0,4,8,12
    const int br = tid >> 5;          // 0..7   (rows br, br+8)
    const int bcn = (tid & 31) * 4;   // 0..124

    float acc[2][8][4];
    #pragma unroll
    for (int mt = 0; mt < 2; mt++)
        #pragma unroll
        for (int nt = 0; nt < 8; nt++)
            #pragma unroll
            for (int r = 0; r < 4; r++) acc[mt][nt][r] = 0.f;

    const bool bok = (n0 + bcn + 3) < N;
    const float4 zero4 = make_float4(0.f, 0.f, 0.f, 0.f);

    const int arow0 = m0 + ar;
    const int arow1 = m0 + ar + 64;
    const float* Bb = B + (size_t)br * N + n0 + bcn;

    float4 av0, av1, bv0, bv1;

    av0 = load_a4(A, arow0, ac, K, amode);
    av1 = load_a4(A, arow1, ac, K, amode);
    bv0 = bok ? *(const float4*)(Bb) : zero4;
    bv1 = bok ? *(const float4*)(Bb + (size_t)8 * N) : zero4;

    const int ntiles = K / BKT;
    int buf = 0;

    {
        As[0][ac + 0][ar] = f2tf(av0.x);
        As[0][ac + 1][ar] = f2tf(av0.y);
        As[0][ac + 2][ar] = f2tf(av0.z);
        As[0][ac + 3][ar] = f2tf(av0.w);
        As[0][ac + 0][ar + 64] = f2tf(av1.x);
        As[0][ac + 1][ar + 64] = f2tf(av1.y);
        As[0][ac + 2][ar + 64] = f2tf(av1.z);
        As[0][ac + 3][ar + 64] = f2tf(av1.w);
        Bs[0][br][bcn + 0] = f2tf(bv0.x);
        Bs[0][br][bcn + 1] = f2tf(bv0.y);
        Bs[0][br][bcn + 2] = f2tf(bv0.z);
        Bs[0][br][bcn + 3] = f2tf(bv0.w);
        Bs[0][br + 8][bcn + 0] = f2tf(bv1.x);
        Bs[0][br + 8][bcn + 1] = f2tf(bv1.y);
        Bs[0][br + 8][bcn + 2] = f2tf(bv1.z);
        Bs[0][br + 8][bcn + 3] = f2tf(bv1.w);
    }
    __syncthreads();

    for (int t = 0; t < ntiles; t++) {
        if (t + 1 < ntiles) {
            const int k0 = (t + 1) * BKT;
            av0 = load_a4(A, arow0, k0 + ac, K, amode);
            av1 = load_a4(A, arow1, k0 + ac, K, amode);
            bv0 = bok ? *(const float4*)(Bb + (size_t)k0 * N) : zero4;
            bv1 = bok ? *(const float4*)(Bb + (size_t)(k0 + 8) * N) : zero4;
        }

        #pragma unroll
        for (int ks = 0; ks < BKT; ks += 8) {
            uint32_t afr[2][4];
            #pragma unroll
            for (int mt = 0; mt < 2; mt++) {
                const int mb = warpM + mt * 16;
                afr[mt][0] = As[buf][ks + tig    ][mb + g];
                afr[mt][1] = As[buf][ks + tig    ][mb + g + 8];
                afr[mt][2] = As[buf][ks + tig + 4][mb + g];
                afr[mt][3] = As[buf][ks + tig + 4][mb + g + 8];
            }
            uint32_t bfr[8][2];
            #pragma unroll
            for (int nt = 0; nt < 8; nt++) {
                const int nb = warpN + nt * 8;
                bfr[nt][0] = Bs[buf][ks + tig    ][nb + g];
                bfr[nt][1] = Bs[buf][ks + tig + 4][nb + g];
            }
            #pragma unroll
            for (int mt = 0; mt < 2; mt++)
                #pragma unroll
                for (int nt = 0; nt < 8; nt++)
                    mma_tf32(acc[mt][nt], afr[mt], bfr[nt]);
        }

        if (t + 1 < ntiles) {
            const int nb = buf ^ 1;
            As[nb][ac + 0][ar] = f2tf(av0.x);
            As[nb][ac + 1][ar] = f2tf(av0.y);
            As[nb][ac + 2][ar] = f2tf(av0.z);
            As[nb][ac + 3][ar] = f2tf(av0.w);
            As[nb][ac + 0][ar + 64] = f2tf(av1.x);
            As[nb][ac + 1][ar + 64] = f2tf(av1.y);
            As[nb][ac + 2][ar + 64] = f2tf(av1.z);
            As[nb][ac + 3][ar + 64] = f2tf(av1.w);
            Bs[nb][br][bcn + 0] = f2tf(bv0.x);
            Bs[nb][br][bcn + 1] = f2tf(bv0.y);
            Bs[nb][br][bcn + 2] = f2tf(bv0.z);
            Bs[nb][br][bcn + 3] = f2tf(bv0.w);
            Bs[nb][br + 8][bcn + 0] = f2tf(bv1.x);
            Bs[nb][br + 8][bcn + 1] = f2tf(bv1.y);
            Bs[nb][br + 8][bcn + 2] = f2tf(bv1.z);
            Bs[nb][br + 8][bcn + 3] = f2tf(bv1.w);
            __syncthreads();
            buf = nb;
        }
    }

    #pragma unroll
    for (int mt = 0; mt < 2; mt++) {
        #pragma unroll
        for (int nt = 0; nt < 8; nt++) {
            const int mA = m0 + warpM + mt * 16 + g;
            const int mB = mA + 8;
            const int n  = n0 + warpN + nt * 8 + tig * 2;
            #pragma unroll
            for (int half = 0; half < 2; half++) {
                const int m = half ? mB : mA;
                float v0 = half ? acc[mt][nt][2] : acc[mt][nt][0];
                float v1 = half ? acc[mt][nt][3] : acc[mt][nt][1];
                if (n < N) {
                    v0 = epi_apply(v0, mode, n, N, m, bias, res);
                    C[(size_t)m * N + n] = v0;
                }
                if (n + 1 < N) {
                    v1 = epi_apply(v1, mode, n + 1, N, m, bias, res);
                    C[(size_t)m * N + n + 1] = v1;
                }
            }
        }
    }
}

// ---------------------------------------------------------------------------
// RMSNorm (warp per token, D=384 -> 12 elems/lane)
// ---------------------------------------------------------------------------
__global__ void rmsnorm_kernel(const float* __restrict__ x,
                               const float* __restrict__ w,
                               float* __restrict__ out)
{
    const int warp = (blockIdx.x * blockDim.x + threadIdx.x) >> 5;
    const int lane = threadIdx.x & 31;
    if (warp >= TOK) return;
    const float* row = x + (size_t)warp * DMODEL;
    float ss = 0.f;
    float v[12];
    #pragma unroll
    for (int c = 0; c < 12; c++) {
        v[c] = row[lane + c * 32];
        ss += v[c] * v[c];
    }
    #pragma unroll
    for (int o = 16; o; o >>= 1) ss += __shfl_xor_sync(0xffffffffu, ss, o);
    const float inv = rsqrtf(ss * (1.f / DMODEL) + 1e-6f);
    float* orow = out + (size_t)warp * DMODEL;
    #pragma unroll
    for (int c = 0; c < 12; c++) {
        const int i = lane + c * 32;
        orow[i] = v[c] * inv * w[i];
    }
}

// ---------------------------------------------------------------------------
// Chunked selective scan.
// Phase 1: per (b, chunk, d, n): local scan with h_in = 0.
// ---------------------------------------------------------------------------
__global__ void scan_chunk_kernel(const float* __restrict__ xc,
                                  const float* __restrict__ dsp_,
                                  const float* __restrict__ bc,
                                  const float* __restrict__ A_log,
                                  const float* __restrict__ Dp,
                                  float* __restrict__ yloc,
                                  float* __restrict__ pa,
                                  float* __restrict__ he)
{
    const int idx = blockIdx.x * blockDim.x + threadIdx.x;
    const int n = idx & 15;
    const int grp = idx >> 4;              // (b*CH + c)*INNER + d
    const int d = grp % INNER;
    const int bch = grp / INNER;           // b*CH + c
    const int c = bch & (CH - 1);
    const int b = bch >> 4;                // CH == 16

    const float A = -__expf(A_log[d * STATE + n]);
    const float Dv = Dp[d];
    float S = 0.f, s = 0.f;

    size_t tok = (size_t)b * SEQ + (size_t)c * CT;

    float dsp = dsp_[tok * INNER + d];
    float xv  = xc[tok * INNER + d];
    float Bv  = bc[tok * 2 * STATE + n];
    float Cv  = bc[tok * 2 * STATE + STATE + n];

    for (int t = 0; t < CT; t++) {
        float dsp_nx = 0.f, x_nx = 0.f, b_nx = 0.f, c_nx = 0.f;
        if (t + 1 < CT) {
            const size_t tk = tok + 1;
            dsp_nx = dsp_[tk * INNER + d];
            x_nx   = xc[tk * INNER + d];
            b_nx   = bc[tk * 2 * STATE + n];
            c_nx   = bc[tk * 2 * STATE + STATE + n];
        }
        S += dsp;
        const float a = __expf(A * dsp);
        s = a * s + dsp * Bv * xv;
        float p = Cv * s;
        p += __shfl_xor_sync(0xffffffffu, p, 8);
        p += __shfl_xor_sync(0xffffffffu, p, 4);
        p += __shfl_xor_sync(0xffffffffu, p, 2);
        p += __shfl_xor_sync(0xffffffffu, p, 1);
        if (n == 0)
            yloc[tok * INNER + d] = p + Dv * xv;
        tok++;
        dsp = dsp_nx; xv = x_nx; Bv = b_nx; Cv = c_nx;
    }

    const size_t o = (size_t)grp * STATE + n;
    pa[o] = __expf(A * S);
    he[o] = s;
}

// ---------------------------------------------------------------------------
// Phase 2: sequential combine over chunks. thread per (b, d, n).
// ---------------------------------------------------------------------------
__global__ void scan_combine_kernel(const float* __restrict__ pa,
                                    const float* __restrict__ he,
                                    float* __restrict__ hin)
{
    const int idx = blockIdx.x * blockDim.x + threadIdx.x;
    if (idx >= BATCH * INNER * STATE) return;
    const int n = idx & 15;
    const int grp = idx >> 4;              // b*INNER + d
    const int d = grp % INNER;
    const int b = grp / INNER;

    float h = 0.f;
    #pragma unroll
    for (int c = 0; c < CH; c++) {
        const size_t o = (((size_t)(b * CH + c) * INNER) + d) * STATE + n;
        hin[o] = h;
        h = pa[o] * h + he[o];
    }
}

// ---------------------------------------------------------------------------
// Phase 3: add cross-chunk correction, apply silu(z) gate.
// ---------------------------------------------------------------------------
__global__ void scan_fixup_kernel(const float* __restrict__ dsp_,
                                  const float* __restrict__ bc,
                                  const float* __restrict__ A_log,
                                  const float* __restrict__ hin,
                                  const float* __restrict__ yloc,
                                  const float* __restrict__ xz,
                                  float* __restrict__ y)
{
    const int idx = blockIdx.x * blockDim.x + threadIdx.x;
    const int n = idx & 15;
    const int grp = idx >> 4;              // (b*CH + c)*INNER + d
    const int d = grp % INNER;
    const int bch = grp / INNER;
    const int c = bch & (CH - 1);
    const int b = bch >> 4;

    const float A = -__expf(A_log[d * STATE + n]);
    const float h0 = hin[(size_t)grp * STATE + n];
    float S = 0.f;

    size_t tok = (size_t)b * SEQ + (size_t)c * CT;

    float dsp = dsp_[tok * INNER + d];
    float Cv  = bc[tok * 2 * STATE + STATE + n];

    for (int t = 0; t < CT; t++) {
        float dsp_nx = 0.f, c_nx = 0.f;
        if (t + 1 < CT) {
            const size_t tk = tok + 1;
            dsp_nx = dsp_[tk * INNER + d];
            c_nx   = bc[tk * 2 * STATE + STATE + n];
        }
        S += dsp;
        float p = Cv * __expf(A * S) * h0;
        p += __shfl_xor_sync(0xffffffffu, p, 8);
        p += __shfl_xor_sync(0xffffffffu, p, 4);
        p += __shfl_xor_sync(0xffffffffu, p, 2);
        p += __shfl_xor_sync(0xffffffffu, p, 1);
        if (n == 0) {
            const float zv = xz[tok * 2 * INNER + INNER + d];
            const float sz = zv / (1.f + __expf(-zv));
            y[tok * INNER + d] = (yloc[tok * INNER + d] + p) * sz;
        }
        tok++;
        dsp = dsp_nx; Cv = c_nx;
    }
}

// ---------------------------------------------------------------------------
// Fused: x2 = xres + LayerNorm(o)*gamma+beta ; h2 = RMSNorm(x2)*rms_w
// ---------------------------------------------------------------------------
__global__ void ln_residual_rms_kernel(const float* __restrict__ o_,
                                       const float* __restrict__ xres,
                                       const float* __restrict__ gamma,
                                       const float* __restrict__ beta,
                                       const float* __restrict__ rms_w,
                                       float* __restrict__ x2,
                                       float* __restrict__ h2)
{
    const int warp = (blockIdx.x * blockDim.x + threadIdx.x) >> 5;
    const int lane = threadIdx.x & 31;
    if (warp >= TOK) return;
    const size_t row = (size_t)warp * DMODEL;

    float o[12];
    float mu = 0.f;
    #pragma unroll
    for (int c = 0; c < 12; c++) {
        o[c] = o_[row + lane + c * 32];
        mu += o[c];
    }
    #pragma unroll
    for (int s = 16; s; s >>= 1) mu += __shfl_xor_sync(0xffffffffu, mu, s);
    mu *= (1.f / DMODEL);

    float var = 0.f;
    #pragma unroll
    for (int c = 0; c < 12; c++) {
        const float dd = o[c] - mu;
        var += dd * dd;
    }
    #pragma unroll
    for (int s = 16; s; s >>= 1) var += __shfl_xor_sync(0xffffffffu, var, s);
    var *= (1.f / DMODEL);
    const float inv = rsqrtf(var + 1e-5f);

    float r[12];
    float ss = 0.f;
    #pragma unroll
    for (int c = 0; c < 12; c++) {
        const int i = lane + c * 32;
        const float v = xres[row + i] + (o[c] - mu) * inv * gamma[i] + beta[i];
        r[c] = v;
        x2[row + i] = v;
        ss += v * v;
    }
    #pragma unroll
    for (int s = 16; s; s >>= 1) ss += __shfl_xor_sync(0xffffffffu, ss, s);
    const float rinv = rsqrtf(ss * (1.f / DMODEL) + 1e-6f);
    #pragma unroll
    for (int c = 0; c < 12; c++) {
        const int i = lane + c * 32;
        h2[row + i] = r[c] * rinv * rms_w[i];
    }
}

// ---------------------------------------------------------------------------
// launch
// ---------------------------------------------------------------------------
static inline float* sym(const void* symbol)
{
    void* p = nullptr;
    cudaGetSymbolAddress(&p, symbol);
    return (float*)p;
}

extern "C" void kernel_launch(void* const* d_in, const int* in_sizes, int n_in,
                              void* d_out, int out_size)
{
    const float* x        = (const float*)d_in[0];
    const float* rms1_w   = (const float*)d_in[1];
    const float* rms2_w   = (const float*)d_in[2];
    const float* in_proj  = (const float*)d_in[3];
    const float* conv_w   = (const float*)d_in[4];
    const float* conv_b   = (const float*)d_in[5];
    const float* x_proj   = (const float*)d_in[6];
    const float* dt_proj  = (const float*)d_in[7];
    const float* dt_b     = (const float*)d_in[8];
    const float* A_log    = (const float*)d_in[9];
    const float* D_param  = (const float*)d_in[10];
    const float* out_proj = (const float*)d_in[11];
    const float* ln_g     = (const float*)d_in[12];
    const float* ln_b     = (const float*)d_in[13];
    const float* gate_w   = (const float*)d_in[14];
    const float* up_w     = (const float*)d_in[15];
    const float* down_w   = (const float*)d_in[16];
    float* out = (float*)d_out;

    float* h    = sym(g_h);
    float* xz   = sym(g_xz);
    float* xc   = sym(g_xc);
    float* bcp  = sym(g_bc);
    float* dl   = sym(g_dl);
    float* y    = sym(g_y);
    float* o    = sym(g_o);
    float* x2   = sym(g_x2);
    float* h2   = sym(g_h2);
    float* gate = sym(g_gate);
    float* hid  = sym(g_hid);
    float* pa   = sym(g_pa);
    float* he   = sym(g_he);
    float* hin  = sym(g_hin);

    const dim3 tpb(256);

    // 1. h = rmsnorm(x) * rms1_w
    rmsnorm_kernel<<<TOK / 8, 256>>>(x, rms1_w, h);

    // 2. xz = h @ in_proj_w   [8192,1536] K=384
    mma_gemm_kernel<<<dim3((2 * INNER) / BN, TOK / BM), tpb>>>(
        h, in_proj, xz, TOK, 2 * INNER, DMODEL, 0, nullptr, nullptr, 0);

    // 3+4. xc = silu(conv(x_inner) + conv_b) — im2col folded into A-load
    mma_gemm_kernel<<<dim3(INNER / BN, TOK / BM), tpb>>>(
        xz, conv_w, xc, TOK, INNER, KW * INNER, 1, conv_b, nullptr, 1);

    // 5. bc = xc @ x_proj_w   [8192,32]  K=768
    mma_gemm_kernel<<<dim3(1, TOK / BM), tpb>>>(
        xc, x_proj, bcp, TOK, 2 * STATE, INNER, 0, nullptr, nullptr, 0);

    // 6. dsp = softplus(xc @ dt_proj_w + dt_b)   K=768
    mma_gemm_kernel<<<dim3(INNER / BN, TOK / BM), tpb>>>(
        xc, dt_proj, dl, TOK, INNER, INNER, 4, dt_b, nullptr, 0);

    // 7. chunked selective scan + gating
    scan_chunk_kernel<<<(BATCH * CH * INNER * STATE) / 256, tpb>>>(
        xc, dl, bcp, A_log, D_param, y, pa, he);
    scan_combine_kernel<<<(BATCH * INNER * STATE + 255) / 256, tpb>>>(
        pa, he, hin);
    scan_fixup_kernel<<<(BATCH * CH * INNER * STATE) / 256, tpb>>>(
        dl, bcp, A_log, hin, y, xz, y);

    // 8. o = y @ out_proj_w   [8192,384] K=768
    mma_gemm_kernel<<<dim3(DMODEL / BN, TOK / BM), tpb>>>(
        y, out_proj, o, TOK, DMODEL, INNER, 0, nullptr, nullptr, 0);

    // 9. x2 = x + LN(o); h2 = RMSNorm(x2)
    ln_residual_rms_kernel<<<TOK / 8, 256>>>(o, x, ln_g, ln_b, rms2_w, x2, h2);

    // 10. gate GEMM  K=384
    mma_gemm_kernel<<<dim3(FFN / BN, TOK / BM), tpb>>>(
        h2, gate_w, gate, TOK, FFN, DMODEL, 0, nullptr, nullptr, 0);
    // 11. hid = silu(gate) * (h2 @ up_w)   (fused)
    mma_gemm_kernel<<<dim3(FFN / BN, TOK / BM), tpb>>>(
        h2, up_w, hid, TOK, FFN, DMODEL, 5, nullptr, gate, 0);

    // 12. out = x2 + hid @ down_w   K=1024
    mma_gemm_kernel<<<dim3(DMODEL / BN, TOK / BM), tpb>>>(
        hid, down_w, out, TOK, DMODEL, FFN, 3, nullptr, x2, 0);
}

// round 11
// speedup vs baseline: 1.7704x; 1.4743x over previous
#include <cuda_runtime.h>
#include <cuda_bf16.h>
#include <cstdint>
#include <cstddef>

// ---------------------------------------------------------------------------
// Problem dims (fixed)
// ---------------------------------------------------------------------------
#define BATCH   4
#define SEQ     2048
#define TOK     (BATCH * SEQ)      // 8192
#define DMODEL  384
#define INNER   768
#define STATE   16
#define KW      4
#define FFN     1024

// scan chunking
#define CH      16                 // chunks per sequence
#define CT      (SEQ / CH)         // 128 steps per chunk

#define NCAT    (2 * STATE + INNER)   // 800: merged x_proj|dt_proj output

// ---------------------------------------------------------------------------
// Scratch (device globals; no allocation allowed)
// ---------------------------------------------------------------------------
__device__ float g_h   [TOK * DMODEL];        // rms1 out
__device__ float g_xz  [TOK * 2 * INNER];     // in_proj out (x_inner | z)
__device__ float g_xs  [TOK * KW * INNER];    // im2col shifted input for conv
__device__ float g_xc  [TOK * INNER];         // conv out (silu)
__device__ float g_bc  [TOK * 2 * STATE];     // x_proj out (B | C)
__device__ float g_dl  [TOK * INNER];         // dsp = softplus(delta)
__device__ float g_y   [TOK * INNER];         // gated scan output
__device__ float g_o   [TOK * DMODEL];        // out_proj result
__device__ float g_x2  [TOK * DMODEL];        // residual after mamba
__device__ float g_h2  [TOK * DMODEL];        // rms2 out
__device__ float g_gate[TOK * FFN];
__device__ float g_hid [TOK * FFN];
__device__ float g_pa  [BATCH * CH * INNER * STATE];  // chunk propagator
__device__ float g_he  [BATCH * CH * INNER * STATE];  // chunk end state (local)
__device__ float g_hin [BATCH * CH * INNER * STATE];  // state entering chunk
__device__ float g_wcat[INNER * NCAT];                // [x_proj | dt_proj]

// ---------------------------------------------------------------------------
// TF32 tensor-core GEMM: C[M,N] = A[M,K] @ B[K,N], row-major. (R6 mainloop)
// CTA tile 128x128, BK=16 double-buffered, 8 warps each 32(M)x64(N),
// mma.sync.aligned.m16n8k8.row.col.f32.tf32.tf32.f32
// Requirements: M % 128 == 0, K % 16 == 0, N % 4 == 0 (guards on N only).
// mode: 0 = store, 1 = silu(acc+bias), 2 = acc+bias, 3 = acc + res[m*N+n],
//       4 = softplus(acc+bias), 5 = silu(res)*acc,
//       6 = merged bc|dsp epilogue: n<32 -> aux[m*32+n] = acc (raw);
//           n>=32 -> C[m*INNER + n-32] = softplus(acc + bias[n-32])
// ---------------------------------------------------------------------------
#define BM 128
#define BN 128
#define BKT 16
#define LDA (BM + 4)
#define LDB (BN + 4)

__device__ __forceinline__ uint32_t f2tf(float f)
{
    uint32_t u;
    asm("cvt.rna.tf32.f32 %0, %1;" : "=r"(u) : "f"(f));
    return u;
}

__device__ __forceinline__ void mma_tf32(float c[4], const uint32_t a[4],
                                         const uint32_t b[2])
{
    asm volatile(
        "mma.sync.aligned.m16n8k8.row.col.f32.tf32.tf32.f32 "
        "{%0,%1,%2,%3}, {%4,%5,%6,%7}, {%8,%9}, {%0,%1,%2,%3};\n"
        : "+f"(c[0]), "+f"(c[1]), "+f"(c[2]), "+f"(c[3])
        : "r"(a[0]), "r"(a[1]), "r"(a[2]), "r"(a[3]),
          "r"(b[0]), "r"(b[1]));
}

__device__ __forceinline__ void epi_store(float v, int mode, int n, int N,
                                          int m, const float* __restrict__ bias,
                                          const float* __restrict__ res,
                                          float* __restrict__ C,
                                          float* __restrict__ aux)
{
    if (mode == 6) {
        if (n < 2 * STATE) {
            aux[(size_t)m * (2 * STATE) + n] = v;
        } else {
            const int nd = n - 2 * STATE;
            float t = v + bias[nd];
            t = (t > 20.f) ? t : log1pf(__expf(t));
            C[(size_t)m * INNER + nd] = t;
        }
        return;
    }
    if (mode == 1) {
        v += bias[n];
        v = v / (1.f + __expf(-v));
    } else if (mode == 2) {
        v += bias[n];
    } else if (mode == 3) {
        v += res[(size_t)m * N + n];
    } else if (mode == 4) {
        v += bias[n];
        v = (v > 20.f) ? v : log1pf(__expf(v));
    } else if (mode == 5) {
        const float gv = res[(size_t)m * N + n];
        v *= gv / (1.f + __expf(-gv));
    }
    C[(size_t)m * N + n] = v;
}

__global__ __launch_bounds__(256, 2) void mma_gemm_kernel(
    const float* __restrict__ A, const float* __restrict__ B,
    float* __restrict__ C, int M, int N, int K,
    int mode, const float* __restrict__ bias, const float* __restrict__ res,
    float* __restrict__ aux)
{
    __shared__ uint32_t As[2][BKT][LDA];
    __shared__ uint32_t Bs[2][BKT][LDB];

    const int tid  = threadIdx.x;
    const int wid  = tid >> 5;
    const int lane = tid & 31;
    const int g    = lane >> 2;   // 0..7
    const int tig  = lane & 3;    // 0..3

    const int warpM = (wid & 3) * 32;
    const int warpN = (wid >> 2) * 64;

    const int m0 = blockIdx.y * BM;
    const int n0 = blockIdx.x * BN;

    const int ar = tid >> 2;          // 0..63  (rows ar, ar+64)
    const int ac = (tid & 3) * 4;     // 0,4,8,12
    const int br = tid >> 5;          // 0..7   (rows br, br+8)
    const int bcn = (tid & 31) * 4;   // 0..124

    float acc[2][8][4];
    #pragma unroll
    for (int mt = 0; mt < 2; mt++)
        #pragma unroll
        for (int nt = 0; nt < 8; nt++)
            #pragma unroll
            for (int r = 0; r < 4; r++) acc[mt][nt][r] = 0.f;

    const bool bok = (n0 + bcn + 3) < N;
    const float4 zero4 = make_float4(0.f, 0.f, 0.f, 0.f);

    const float* Ab = A + (size_t)(m0 + ar) * K + ac;
    const float* Bb = B + (size_t)br * N + n0 + bcn;

    float4 av0, av1, bv0, bv1;

    av0 = *(const float4*)(Ab);
    av1 = *(const float4*)(Ab + (size_t)64 * K);
    bv0 = bok ? *(const float4*)(Bb) : zero4;
    bv1 = bok ? *(const float4*)(Bb + (size_t)8 * N) : zero4;

    const int ntiles = K / BKT;
    int buf = 0;

    {
        As[0][ac + 0][ar] = f2tf(av0.x);
        As[0][ac + 1][ar] = f2tf(av0.y);
        As[0][ac + 2][ar] = f2tf(av0.z);
        As[0][ac + 3][ar] = f2tf(av0.w);
        As[0][ac + 0][ar + 64] = f2tf(av1.x);
        As[0][ac + 1][ar + 64] = f2tf(av1.y);
        As[0][ac + 2][ar + 64] = f2tf(av1.z);
        As[0][ac + 3][ar + 64] = f2tf(av1.w);
        Bs[0][br][bcn + 0] = f2tf(bv0.x);
        Bs[0][br][bcn + 1] = f2tf(bv0.y);
        Bs[0][br][bcn + 2] = f2tf(bv0.z);
        Bs[0][br][bcn + 3] = f2tf(bv0.w);
        Bs[0][br + 8][bcn + 0] = f2tf(bv1.x);
        Bs[0][br + 8][bcn + 1] = f2tf(bv1.y);
        Bs[0][br + 8][bcn + 2] = f2tf(bv1.z);
        Bs[0][br + 8][bcn + 3] = f2tf(bv1.w);
    }
    __syncthreads();

    for (int t = 0; t < ntiles; t++) {
        if (t + 1 < ntiles) {
            const int k0 = (t + 1) * BKT;
            av0 = *(const float4*)(Ab + k0);
            av1 = *(const float4*)(Ab + k0 + (size_t)64 * K);
            bv0 = bok ? *(const float4*)(Bb + (size_t)k0 * N) : zero4;
            bv1 = bok ? *(const float4*)(Bb + (size_t)(k0 + 8) * N) : zero4;
        }

        #pragma unroll
        for (int ks = 0; ks < BKT; ks += 8) {
            uint32_t afr[2][4];
            #pragma unroll
            for (int mt = 0; mt < 2; mt++) {
                const int mb = warpM + mt * 16;
                afr[mt][0] = As[buf][ks + tig    ][mb + g];
                afr[mt][1] = As[buf][ks + tig    ][mb + g + 8];
                afr[mt][2] = As[buf][ks + tig + 4][mb + g];
                afr[mt][3] = As[buf][ks + tig + 4][mb + g + 8];
            }
            uint32_t bfr[8][2];
            #pragma unroll
            for (int nt = 0; nt < 8; nt++) {
                const int nb = warpN + nt * 8;
                bfr[nt][0] = Bs[buf][ks + tig    ][nb + g];
                bfr[nt][1] = Bs[buf][ks + tig + 4][nb + g];
            }
            #pragma unroll
            for (int mt = 0; mt < 2; mt++)
                #pragma unroll
                for (int nt = 0; nt < 8; nt++)
                    mma_tf32(acc[mt][nt], afr[mt], bfr[nt]);
        }

        if (t + 1 < ntiles) {
            const int nb = buf ^ 1;
            As[nb][ac + 0][ar] = f2tf(av0.x);
            As[nb][ac + 1][ar] = f2tf(av0.y);
            As[nb][ac + 2][ar] = f2tf(av0.z);
            As[nb][ac + 3][ar] = f2tf(av0.w);
            As[nb][ac + 0][ar + 64] = f2tf(av1.x);
            As[nb][ac + 1][ar + 64] = f2tf(av1.y);
            As[nb][ac + 2][ar + 64] = f2tf(av1.z);
            As[nb][ac + 3][ar + 64] = f2tf(av1.w);
            Bs[nb][br][bcn + 0] = f2tf(bv0.x);
            Bs[nb][br][bcn + 1] = f2tf(bv0.y);
            Bs[nb][br][bcn + 2] = f2tf(bv0.z);
            Bs[nb][br][bcn + 3] = f2tf(bv0.w);
            Bs[nb][br + 8][bcn + 0] = f2tf(bv1.x);
            Bs[nb][br + 8][bcn + 1] = f2tf(bv1.y);
            Bs[nb][br + 8][bcn + 2] = f2tf(bv1.z);
            Bs[nb][br + 8][bcn + 3] = f2tf(bv1.w);
            __syncthreads();
            buf = nb;
        }
    }

    #pragma unroll
    for (int mt = 0; mt < 2; mt++) {
        #pragma unroll
        for (int nt = 0; nt < 8; nt++) {
            const int mA = m0 + warpM + mt * 16 + g;
            const int mB = mA + 8;
            const int n  = n0 + warpN + nt * 8 + tig * 2;
            #pragma unroll
            for (int half = 0; half < 2; half++) {
                const int m = half ? mB : mA;
                float v0 = half ? acc[mt][nt][2] : acc[mt][nt][0];
                float v1 = half ? acc[mt][nt][3] : acc[mt][nt][1];
                if (n < N)
                    epi_store(v0, mode, n, N, m, bias, res, C, aux);
                if (n + 1 < N)
                    epi_store(v1, mode, n + 1, N, m, bias, res, C, aux);
            }
        }
    }
}

// ---------------------------------------------------------------------------
// Build wcat = [x_proj (768x32) | dt_proj (768x768)] -> [768 x 800]
// ---------------------------------------------------------------------------
__global__ void wcat_fill_kernel(const float* __restrict__ x_proj,
                                 const float* __restrict__ dt_proj,
                                 float* __restrict__ wcat)
{
    const int idx = blockIdx.x * blockDim.x + threadIdx.x;
    if (idx >= INNER * NCAT) return;
    const int k = idx / NCAT;
    const int n = idx - k * NCAT;
    wcat[idx] = (n < 2 * STATE) ? x_proj[k * 2 * STATE + n]
                                : dt_proj[k * INNER + (n - 2 * STATE)];
}

// ---------------------------------------------------------------------------
// RMSNorm (warp per token, D=384 -> 12 elems/lane)
// ---------------------------------------------------------------------------
__global__ void rmsnorm_kernel(const float* __restrict__ x,
                               const float* __restrict__ w,
                               float* __restrict__ out)
{
    const int warp = (blockIdx.x * blockDim.x + threadIdx.x) >> 5;
    const int lane = threadIdx.x & 31;
    if (warp >= TOK) return;
    const float* row = x + (size_t)warp * DMODEL;
    float ss = 0.f;
    float v[12];
    #pragma unroll
    for (int c = 0; c < 12; c++) {
        v[c] = row[lane + c * 32];
        ss += v[c] * v[c];
    }
    #pragma unroll
    for (int o = 16; o; o >>= 1) ss += __shfl_xor_sync(0xffffffffu, ss, o);
    const float inv = rsqrtf(ss * (1.f / DMODEL) + 1e-6f);
    float* orow = out + (size_t)warp * DMODEL;
    #pragma unroll
    for (int c = 0; c < 12; c++) {
        const int i = lane + c * 32;
        orow[i] = v[c] * inv * w[i];
    }
}

// ---------------------------------------------------------------------------
// im2col for conv: xs[tok, w*INNER + i] = x_inner[b, t-1+w, i] (0 outside seq)
// ---------------------------------------------------------------------------
__global__ void conv_shift_kernel(const float* __restrict__ xz,
                                  float* __restrict__ xs)
{
    const int idx = blockIdx.x * blockDim.x + threadIdx.x;   // float4 id
    const int total = TOK * KW * INNER / 4;
    if (idx >= total) return;
    const int e = idx * 4;
    const int tok = e / (KW * INNER);
    const int c = e - tok * (KW * INNER);
    const int w = c / INNER;
    const int i = c - w * INNER;
    const int b = tok >> 11;
    const int t = tok & (SEQ - 1);
    const int ts = t - 1 + w;
    float4 v = make_float4(0.f, 0.f, 0.f, 0.f);
    if (ts >= 0 && ts < SEQ)
        v = *(const float4*)(xz + ((size_t)(b * SEQ + ts)) * (2 * INNER) + i);
    *(float4*)(xs + (size_t)e) = v;
}

// ---------------------------------------------------------------------------
// Chunked selective scan.
// Phase 1: per (b, chunk, d, n): local scan with h_in = 0.
// ---------------------------------------------------------------------------
__global__ void scan_chunk_kernel(const float* __restrict__ xc,
                                  const float* __restrict__ dsp_,
                                  const float* __restrict__ bc,
                                  const float* __restrict__ A_log,
                                  const float* __restrict__ Dp,
                                  float* __restrict__ yloc,
                                  float* __restrict__ pa,
                                  float* __restrict__ he)
{
    const int idx = blockIdx.x * blockDim.x + threadIdx.x;
    const int n = idx & 15;
    const int grp = idx >> 4;              // (b*CH + c)*INNER + d
    const int d = grp % INNER;
    const int bch = grp / INNER;           // b*CH + c
    const int c = bch & (CH - 1);
    const int b = bch >> 4;                // CH == 16

    const float A = -__expf(A_log[d * STATE + n]);
    const float Dv = Dp[d];
    float S = 0.f, s = 0.f;

    size_t tok = (size_t)b * SEQ + (size_t)c * CT;

    float dsp = dsp_[tok * INNER + d];
    float xv  = xc[tok * INNER + d];
    float Bv  = bc[tok * 2 * STATE + n];
    float Cv  = bc[tok * 2 * STATE + STATE + n];

    for (int t = 0; t < CT; t++) {
        float dsp_nx = 0.f, x_nx = 0.f, b_nx = 0.f, c_nx = 0.f;
        if (t + 1 < CT) {
            const size_t tk = tok + 1;
            dsp_nx = dsp_[tk * INNER + d];
            x_nx   = xc[tk * INNER + d];
            b_nx   = bc[tk * 2 * STATE + n];
            c_nx   = bc[tk * 2 * STATE + STATE + n];
        }
        S += dsp;
        const float a = __expf(A * dsp);
        s = a * s + dsp * Bv * xv;
        float p = Cv * s;
        p += __shfl_xor_sync(0xffffffffu, p, 8);
        p += __shfl_xor_sync(0xffffffffu, p, 4);
        p += __shfl_xor_sync(0xffffffffu, p, 2);
        p += __shfl_xor_sync(0xffffffffu, p, 1);
        if (n == 0)
            yloc[tok * INNER + d] = p + Dv * xv;
        tok++;
        dsp = dsp_nx; xv = x_nx; Bv = b_nx; Cv = c_nx;
    }

    const size_t o = (size_t)grp * STATE + n;
    pa[o] = __expf(A * S);
    he[o] = s;
}

// ---------------------------------------------------------------------------
// Phase 2: sequential combine over chunks. thread per (b, d, n).
// ---------------------------------------------------------------------------
__global__ void scan_combine_kernel(const float* __restrict__ pa,
                                    const float* __restrict__ he,
                                    float* __restrict__ hin)
{
    const int idx = blockIdx.x * blockDim.x + threadIdx.x;
    if (idx >= BATCH * INNER * STATE) return;
    const int n = idx & 15;
    const int grp = idx >> 4;              // b*INNER + d
    const int d = grp % INNER;
    const int b = grp / INNER;

    float h = 0.f;
    #pragma unroll
    for (int c = 0; c < CH; c++) {
        const size_t o = (((size_t)(b * CH + c) * INNER) + d) * STATE + n;
        hin[o] = h;
        h = pa[o] * h + he[o];
    }
}

// ---------------------------------------------------------------------------
// Phase 3: add cross-chunk correction, apply silu(z) gate.
// ---------------------------------------------------------------------------
__global__ void scan_fixup_kernel(const float* __restrict__ dsp_,
                                  const float* __restrict__ bc,
                                  const float* __restrict__ A_log,
                                  const float* __restrict__ hin,
                                  const float* __restrict__ yloc,
                                  const float* __restrict__ xz,
                                  float* __restrict__ y)
{
    const int idx = blockIdx.x * blockDim.x + threadIdx.x;
    const int n = idx & 15;
    const int grp = idx >> 4;              // (b*CH + c)*INNER + d
    const int d = grp % INNER;
    const int bch = grp / INNER;
    const int c = bch & (CH - 1);
    const int b = bch >> 4;

    const float A = -__expf(A_log[d * STATE + n]);
    const float h0 = hin[(size_t)grp * STATE + n];
    float S = 0.f;

    size_t tok = (size_t)b * SEQ + (size_t)c * CT;

    float dsp = dsp_[tok * INNER + d];
    float Cv  = bc[tok * 2 * STATE + STATE + n];

    for (int t = 0; t < CT; t++) {
        float dsp_nx = 0.f, c_nx = 0.f;
        if (t + 1 < CT) {
            const size_t tk = tok + 1;
            dsp_nx = dsp_[tk * INNER + d];
            c_nx   = bc[tk * 2 * STATE + STATE + n];
        }
        S += dsp;
        float p = Cv * __expf(A * S) * h0;
        p += __shfl_xor_sync(0xffffffffu, p, 8);
        p += __shfl_xor_sync(0xffffffffu, p, 4);
        p += __shfl_xor_sync(0xffffffffu, p, 2);
        p += __shfl_xor_sync(0xffffffffu, p, 1);
        if (n == 0) {
            const float zv = xz[tok * 2 * INNER + INNER + d];
            const float sz = zv / (1.f + __expf(-zv));
            y[tok * INNER + d] = (yloc[tok * INNER + d] + p) * sz;
        }
        tok++;
        dsp = dsp_nx; Cv = c_nx;
    }
}

// ---------------------------------------------------------------------------
// Fused: x2 = xres + LayerNorm(o)*gamma+beta ; h2 = RMSNorm(x2)*rms_w
// ---------------------------------------------------------------------------
__global__ void ln_residual_rms_kernel(const float* __restrict__ o_,
                                       const float* __restrict__ xres,
                                       const float* __restrict__ gamma,
                                       const float* __restrict__ beta,
                                       const float* __restrict__ rms_w,
                                       float* __restrict__ x2,
                                       float* __restrict__ h2)
{
    const int warp = (blockIdx.x * blockDim.x + threadIdx.x) >> 5;
    const int lane = threadIdx.x & 31;
    if (warp >= TOK) return;
    const size_t row = (size_t)warp * DMODEL;

    float o[12];
    float mu = 0.f;
    #pragma unroll
    for (int c = 0; c < 12; c++) {
        o[c] = o_[row + lane + c * 32];
        mu += o[c];
    }
    #pragma unroll
    for (int s = 16; s; s >>= 1) mu += __shfl_xor_sync(0xffffffffu, mu, s);
    mu *= (1.f / DMODEL);

    float var = 0.f;
    #pragma unroll
    for (int c = 0; c < 12; c++) {
        const float dd = o[c] - mu;
        var += dd * dd;
    }
    #pragma unroll
    for (int s = 16; s; s >>= 1) var += __shfl_xor_sync(0xffffffffu, var, s);
    var *= (1.f / DMODEL);
    const float inv = rsqrtf(var + 1e-5f);

    float r[12];
    float ss = 0.f;
    #pragma unroll
    for (int c = 0; c < 12; c++) {
        const int i = lane + c * 32;
        const float v = xres[row + i] + (o[c] - mu) * inv * gamma[i] + beta[i];
        r[c] = v;
        x2[row + i] = v;
        ss += v * v;
    }
    #pragma unroll
    for (int s = 16; s; s >>= 1) ss += __shfl_xor_sync(0xffffffffu, ss, s);
    const float rinv = rsqrtf(ss * (1.f / DMODEL) + 1e-6f);
    #pragma unroll
    for (int c = 0; c < 12; c++) {
        const int i = lane + c * 32;
        h2[row + i] = r[c] * rinv * rms_w[i];
    }
}

// ---------------------------------------------------------------------------
// launch
// ---------------------------------------------------------------------------
static inline float* sym(const void* symbol)
{
    void* p = nullptr;
    cudaGetSymbolAddress(&p, symbol);
    return (float*)p;
}

extern "C" void kernel_launch(void* const* d_in, const int* in_sizes, int n_in,
                              void* d_out, int out_size)
{
    const float* x        = (const float*)d_in[0];
    const float* rms1_w   = (const float*)d_in[1];
    const float* rms2_w   = (const float*)d_in[2];
    const float* in_proj  = (const float*)d_in[3];
    const float* conv_w   = (const float*)d_in[4];
    const float* conv_b   = (const float*)d_in[5];
    const float* x_proj   = (const float*)d_in[6];
    const float* dt_proj  = (const float*)d_in[7];
    const float* dt_b     = (const float*)d_in[8];
    const float* A_log    = (const float*)d_in[9];
    const float* D_param  = (const float*)d_in[10];
    const float* out_proj = (const float*)d_in[11];
    const float* ln_g     = (const float*)d_in[12];
    const float* ln_b     = (const float*)d_in[13];
    const float* gate_w   = (const float*)d_in[14];
    const float* up_w     = (const float*)d_in[15];
    const float* down_w   = (const float*)d_in[16];
    float* out = (float*)d_out;

    float* h    = sym(g_h);
    float* xz   = sym(g_xz);
    float* xs   = sym(g_xs);
    float* xc   = sym(g_xc);
    float* bcp  = sym(g_bc);
    float* dl   = sym(g_dl);
    float* y    = sym(g_y);
    float* o    = sym(g_o);
    float* x2   = sym(g_x2);
    float* h2   = sym(g_h2);
    float* gate = sym(g_gate);
    float* hid  = sym(g_hid);
    float* pa   = sym(g_pa);
    float* he   = sym(g_he);
    float* hin  = sym(g_hin);
    float* wcat = sym(g_wcat);

    const dim3 tpb(256);

    // 0. wcat = [x_proj | dt_proj]
    wcat_fill_kernel<<<(INNER * NCAT + 255) / 256, tpb>>>(x_proj, dt_proj, wcat);

    // 1. h = rmsnorm(x) * rms1_w
    rmsnorm_kernel<<<TOK / 8, 256>>>(x, rms1_w, h);

    // 2. xz = h @ in_proj_w   [8192,1536] K=384
    mma_gemm_kernel<<<dim3((2 * INNER) / BN, TOK / BM), tpb>>>(
        h, in_proj, xz, TOK, 2 * INNER, DMODEL, 0, nullptr, nullptr, nullptr);

    // 3. im2col shift
    {
        const int total = TOK * KW * INNER / 4;
        conv_shift_kernel<<<(total + 255) / 256, tpb>>>(xz, xs);
    }

    // 4. xc = silu(xs @ conv_w_reshaped + conv_b)   K=3072
    mma_gemm_kernel<<<dim3(INNER / BN, TOK / BM), tpb>>>(
        xs, conv_w, xc, TOK, INNER, KW * INNER, 1, conv_b, nullptr, nullptr);

    // 5+6. merged: [bc | dsp] = xc @ wcat   N=800, K=768  (mode 6)
    mma_gemm_kernel<<<dim3((NCAT + BN - 1) / BN, TOK / BM), tpb>>>(
        xc, wcat, dl, TOK, NCAT, INNER, 6, dt_b, nullptr, bcp);

    // 7. chunked selective scan + gating
    scan_chunk_kernel<<<(BATCH * CH * INNER * STATE) / 256, tpb>>>(
        xc, dl, bcp, A_log, D_param, y, pa, he);
    scan_combine_kernel<<<(BATCH * INNER * STATE + 255) / 256, tpb>>>(
        pa, he, hin);
    scan_fixup_kernel<<<(BATCH * CH * INNER * STATE) / 256, tpb>>>(
        dl, bcp, A_log, hin, y, xz, y);

    // 8. o = y @ out_proj_w   [8192,384] K=768
    mma_gemm_kernel<<<dim3(DMODEL / BN, TOK / BM), tpb>>>(
        y, out_proj, o, TOK, DMODEL, INNER, 0, nullptr, nullptr, nullptr);

    // 9. x2 = x + LN(o); h2 = RMSNorm(x2)
    ln_residual_rms_kernel<<<TOK / 8, 256>>>(o, x, ln_g, ln_b, rms2_w, x2, h2);

    // 10. gate GEMM  K=384
    mma_gemm_kernel<<<dim3(FFN / BN, TOK / BM), tpb>>>(
        h2, gate_w, gate, TOK, FFN, DMODEL, 0, nullptr, nullptr, nullptr);
    // 11. hid = silu(gate) * (h2 @ up_w)   (fused)
    mma_gemm_kernel<<<dim3(FFN / BN, TOK / BM), tpb>>>(
        h2, up_w, hid, TOK, FFN, DMODEL, 5, nullptr, gate, nullptr);

    // 12. out = x2 + hid @ down_w   K=1024
    mma_gemm_kernel<<<dim3(DMODEL / BN, TOK / BM), tpb>>>(
        hid, down_w, out, TOK, DMODEL, FFN, 3, nullptr, x2, nullptr);
}

// round 12
// speedup vs baseline: 2.0493x; 1.1575x over previous
#include <cuda_runtime.h>
#include <cuda_bf16.h>
#include <cstdint>
#include <cstddef>

// ---------------------------------------------------------------------------
// Problem dims (fixed)
// ---------------------------------------------------------------------------
#define BATCH   4
#define SEQ     2048
#define TOK     (BATCH * SEQ)      // 8192
#define DMODEL  384
#define INNER   768
#define STATE   16
#define KW      4
#define FFN     1024

// scan chunking
#define CH      16
#define CT      (SEQ / CH)         // 128

// padded x_proj width
#define NXPAD   128

// ---------------------------------------------------------------------------
// Scratch (device globals; no allocation allowed)
// ---------------------------------------------------------------------------
__device__ float g_h   [TOK * DMODEL];
__device__ float g_xz  [TOK * 2 * INNER];
__device__ float g_xs  [TOK * KW * INNER];
__device__ float g_xc  [TOK * INNER];
__device__ float g_bc  [TOK * 2 * STATE];
__device__ float g_dl  [TOK * INNER];
__device__ float g_y   [TOK * INNER];
__device__ float g_o   [TOK * DMODEL];
__device__ float g_x2  [TOK * DMODEL];
__device__ float g_h2  [TOK * DMODEL];
__device__ float g_gate[TOK * FFN];
__device__ float g_hid [TOK * FFN];
__device__ float g_pa  [BATCH * CH * INNER * STATE];
__device__ float g_he  [BATCH * CH * INNER * STATE];
__device__ float g_hin [BATCH * CH * INNER * STATE];

// tf32-pre-rounded weights
__device__ float g_wip [DMODEL * 2 * INNER];      // 589824
__device__ float g_wcv [KW * INNER * INNER];      // 2359296
__device__ float g_wxp [INNER * NXPAD];           // 98304 (padded)
__device__ float g_wdt [INNER * INNER];           // 589824
__device__ float g_wop [INNER * DMODEL];          // 294912
__device__ float g_wgt [DMODEL * FFN];            // 393216
__device__ float g_wup [DMODEL * FFN];            // 393216
__device__ float g_wdn [FFN * DMODEL];            // 393216

// ---------------------------------------------------------------------------
// helpers
// ---------------------------------------------------------------------------
__device__ __forceinline__ float tf32r(float f)
{
    uint32_t u;
    asm("cvt.rna.tf32.f32 %0, %1;" : "=r"(u) : "f"(f));
    return __uint_as_float(u);
}

__device__ __forceinline__ void mma_tf32(float c[4], const uint32_t a[4],
                                         const uint32_t b[2])
{
    asm volatile(
        "mma.sync.aligned.m16n8k8.row.col.f32.tf32.tf32.f32 "
        "{%0,%1,%2,%3}, {%4,%5,%6,%7}, {%8,%9}, {%0,%1,%2,%3};\n"
        : "+f"(c[0]), "+f"(c[1]), "+f"(c[2]), "+f"(c[3])
        : "r"(a[0]), "r"(a[1]), "r"(a[2]), "r"(a[3]),
          "r"(b[0]), "r"(b[1]));
}

#define CP16(dst, src) \
    asm volatile("cp.async.cg.shared.global [%0], [%1], 16;\n" \
                 :: "r"(dst), "l"(src))
#define CPCOMMIT() asm volatile("cp.async.commit_group;\n")
#define CPWAIT2()  asm volatile("cp.async.wait_group 2;\n")

// ---------------------------------------------------------------------------
// TF32 GEMM, cp.async 4-stage pipeline. All operands pre-rounded to tf32.
// C[M,N?] row-major with logical width Nc (stores guarded n < Nc).
// Requires M%128==0, N%128==0, K%16==0, K/16 >= 3.
// mode: 0 store, 1 silu(acc+bias), 2 acc+bias, 3 acc+res (NO rounding),
//       4 softplus(acc+bias), 5 silu(res)*acc.  Modes != 3 round to tf32.
// ---------------------------------------------------------------------------
#define BM 128
#define BN 128
#define BKT 16
#define STG 4

__global__ __launch_bounds__(256, 2) void mma_gemm_kernel(
    const float* __restrict__ A, const float* __restrict__ B,
    float* __restrict__ C, int M, int N, int K, int Nc,
    int mode, const float* __restrict__ bias, const float* __restrict__ res)
{
    __shared__ float As[STG][128][20];
    __shared__ float Bs[STG][16][132];

    const int tid  = threadIdx.x;
    const int wid  = tid >> 5;
    const int lane = tid & 31;
    const int g    = lane >> 2;
    const int tig  = lane & 3;

    const int warpM = (wid & 3) * 32;
    const int warpN = (wid >> 2) * 64;

    const int m0 = blockIdx.y * BM;
    const int n0 = blockIdx.x * BN;

    const int ar  = tid >> 2;         // 0..63
    const int ac  = (tid & 3) * 4;    // 0,4,8,12
    const int br  = tid >> 5;         // 0..7
    const int bcn = (tid & 31) * 4;   // 0..124

    const float* a0p = A + (size_t)(m0 + ar) * K + ac;
    const float* a1p = A + (size_t)(m0 + ar + 64) * K + ac;
    const float* b0p = B + (size_t)br * N + n0 + bcn;
    const float* b1p = B + (size_t)(br + 8) * N + n0 + bcn;

    uint32_t sa0[STG], sa1[STG], sb0[STG], sb1[STG];
    #pragma unroll
    for (int s = 0; s < STG; s++) {
        sa0[s] = (uint32_t)__cvta_generic_to_shared(&As[s][ar][ac]);
        sa1[s] = (uint32_t)__cvta_generic_to_shared(&As[s][ar + 64][ac]);
        sb0[s] = (uint32_t)__cvta_generic_to_shared(&Bs[s][br][bcn]);
        sb1[s] = (uint32_t)__cvta_generic_to_shared(&Bs[s][br + 8][bcn]);
    }

    float acc[2][8][4];
    #pragma unroll
    for (int mt = 0; mt < 2; mt++)
        #pragma unroll
        for (int nt = 0; nt < 8; nt++)
            #pragma unroll
            for (int r = 0; r < 4; r++) acc[mt][nt][r] = 0.f;

    const int ntiles = K / BKT;

    // prologue: tiles 0..2 -> stages 0..2
    #pragma unroll
    for (int s = 0; s < 3; s++) {
        CP16(sa0[s], a0p + s * 16);
        CP16(sa1[s], a1p + s * 16);
        CP16(sb0[s], b0p + (size_t)(s * 16) * N);
        CP16(sb1[s], b1p + (size_t)(s * 16) * N);
        CPCOMMIT();
    }

    for (int t = 0; t < ntiles; t++) {
        CPWAIT2();               // tile t resident
        __syncthreads();

        const int tn = t + 3;    // stage (t+3)&3 != compute stage t&3
        if (tn < ntiles) {
            const int s = tn & 3;
            CP16(sa0[s], a0p + tn * 16);
            CP16(sa1[s], a1p + tn * 16);
            CP16(sb0[s], b0p + (size_t)(tn * 16) * N);
            CP16(sb1[s], b1p + (size_t)(tn * 16) * N);
        }
        CPCOMMIT();              // one group per iter (possibly empty)

        const int st = t & 3;
        #pragma unroll
        for (int ks = 0; ks < BKT; ks += 8) {
            uint32_t afr[2][4];
            #pragma unroll
            for (int mt = 0; mt < 2; mt++) {
                const int mb = warpM + mt * 16 + g;
                afr[mt][0] = __float_as_uint(As[st][mb    ][ks + tig]);
                afr[mt][1] = __float_as_uint(As[st][mb + 8][ks + tig]);
                afr[mt][2] = __float_as_uint(As[st][mb    ][ks + tig + 4]);
                afr[mt][3] = __float_as_uint(As[st][mb + 8][ks + tig + 4]);
            }
            uint32_t bfr[8][2];
            #pragma unroll
            for (int nt = 0; nt < 8; nt++) {
                const int nb = warpN + nt * 8 + g;
                bfr[nt][0] = __float_as_uint(Bs[st][ks + tig    ][nb]);
                bfr[nt][1] = __float_as_uint(Bs[st][ks + tig + 4][nb]);
            }
            #pragma unroll
            for (int mt = 0; mt < 2; mt++)
                #pragma unroll
                for (int nt = 0; nt < 8; nt++)
                    mma_tf32(acc[mt][nt], afr[mt], bfr[nt]);
        }
    }

    // epilogue
    #pragma unroll
    for (int mt = 0; mt < 2; mt++) {
        #pragma unroll
        for (int nt = 0; nt < 8; nt++) {
            const int mA = m0 + warpM + mt * 16 + g;
            const int n  = n0 + warpN + nt * 8 + tig * 2;
            #pragma unroll
            for (int half = 0; half < 2; half++) {
                const int m = half ? (mA + 8) : mA;
                float v0 = half ? acc[mt][nt][2] : acc[mt][nt][0];
                float v1 = half ? acc[mt][nt][3] : acc[mt][nt][1];
                #pragma unroll
                for (int e = 0; e < 2; e++) {
                    const int nn = n + e;
                    float v = e ? v1 : v0;
                    if (nn >= Nc) continue;
                    if (mode == 1) {
                        v += bias[nn];
                        v = v / (1.f + __expf(-v));
                    } else if (mode == 2) {
                        v += bias[nn];
                    } else if (mode == 3) {
                        v += res[(size_t)m * Nc + nn];
                    } else if (mode == 4) {
                        v += bias[nn];
                        v = (v > 20.f) ? v : log1pf(__expf(v));
                    } else if (mode == 5) {
                        const float gv = res[(size_t)m * Nc + nn];
                        v *= gv / (1.f + __expf(-gv));
                    }
                    if (mode != 3) v = tf32r(v);
                    C[(size_t)m * Nc + nn] = v;
                }
            }
        }
    }
}

// ---------------------------------------------------------------------------
// Pre-round all weights into device globals (single launch).
// x_proj is additionally padded 32 -> 128 columns with zeros.
// ---------------------------------------------------------------------------
#define NIP (DMODEL * 2 * INNER)
#define NCV (KW * INNER * INNER)
#define NXP (INNER * NXPAD)
#define NDT (INNER * INNER)
#define NOP (INNER * DMODEL)
#define NGT (DMODEL * FFN)
#define NTOTW (NIP + NCV + NXP + NDT + NOP + 3 * NGT)

__global__ void prep_weights_kernel(const float* __restrict__ ip,
                                    const float* __restrict__ cv,
                                    const float* __restrict__ xp,
                                    const float* __restrict__ dt,
                                    const float* __restrict__ op,
                                    const float* __restrict__ gt,
                                    const float* __restrict__ up,
                                    const float* __restrict__ dn)
{
    int i = blockIdx.x * blockDim.x + threadIdx.x;
    if (i >= NTOTW) return;
    if (i < NIP) { g_wip[i] = tf32r(ip[i]); return; }
    i -= NIP;
    if (i < NCV) { g_wcv[i] = tf32r(cv[i]); return; }
    i -= NCV;
    if (i < NXP) {
        const int k = i >> 7, n = i & (NXPAD - 1);
        g_wxp[i] = (n < 2 * STATE) ? tf32r(xp[k * 2 * STATE + n]) : 0.f;
        return;
    }
    i -= NXP;
    if (i < NDT) { g_wdt[i] = tf32r(dt[i]); return; }
    i -= NDT;
    if (i < NOP) { g_wop[i] = tf32r(op[i]); return; }
    i -= NOP;
    if (i < NGT) { g_wgt[i] = tf32r(gt[i]); return; }
    i -= NGT;
    if (i < NGT) { g_wup[i] = tf32r(up[i]); return; }
    i -= NGT;
    g_wdn[i] = tf32r(dn[i]);
}

// ---------------------------------------------------------------------------
// RMSNorm (warp per token) — output tf32-rounded (feeds in_proj GEMM)
// ---------------------------------------------------------------------------
__global__ void rmsnorm_kernel(const float* __restrict__ x,
                               const float* __restrict__ w,
                               float* __restrict__ out)
{
    const int warp = (blockIdx.x * blockDim.x + threadIdx.x) >> 5;
    const int lane = threadIdx.x & 31;
    if (warp >= TOK) return;
    const float* row = x + (size_t)warp * DMODEL;
    float ss = 0.f;
    float v[12];
    #pragma unroll
    for (int c = 0; c < 12; c++) {
        v[c] = row[lane + c * 32];
        ss += v[c] * v[c];
    }
    #pragma unroll
    for (int o = 16; o; o >>= 1) ss += __shfl_xor_sync(0xffffffffu, ss, o);
    const float inv = rsqrtf(ss * (1.f / DMODEL) + 1e-6f);
    float* orow = out + (size_t)warp * DMODEL;
    #pragma unroll
    for (int c = 0; c < 12; c++) {
        const int i = lane + c * 32;
        orow[i] = tf32r(v[c] * inv * w[i]);
    }
}

// ---------------------------------------------------------------------------
// im2col shift (values already rounded in xz)
// ---------------------------------------------------------------------------
__global__ void conv_shift_kernel(const float* __restrict__ xz,
                                  float* __restrict__ xs)
{
    const int idx = blockIdx.x * blockDim.x + threadIdx.x;
    const int total = TOK * KW * INNER / 4;
    if (idx >= total) return;
    const int e = idx * 4;
    const int tok = e / (KW * INNER);
    const int c = e - tok * (KW * INNER);
    const int w = c / INNER;
    const int i = c - w * INNER;
    const int b = tok >> 11;
    const int t = tok & (SEQ - 1);
    const int ts = t - 1 + w;
    float4 v = make_float4(0.f, 0.f, 0.f, 0.f);
    if (ts >= 0 && ts < SEQ)
        v = *(const float4*)(xz + ((size_t)(b * SEQ + ts)) * (2 * INNER) + i);
    *(float4*)(xs + (size_t)e) = v;
}

// ---------------------------------------------------------------------------
// Chunked selective scan (unchanged from R6)
// ---------------------------------------------------------------------------
__global__ void scan_chunk_kernel(const float* __restrict__ xc,
                                  const float* __restrict__ dsp_,
                                  const float* __restrict__ bc,
                                  const float* __restrict__ A_log,
                                  const float* __restrict__ Dp,
                                  float* __restrict__ yloc,
                                  float* __restrict__ pa,
                                  float* __restrict__ he)
{
    const int idx = blockIdx.x * blockDim.x + threadIdx.x;
    const int n = idx & 15;
    const int grp = idx >> 4;
    const int d = grp % INNER;
    const int bch = grp / INNER;
    const int c = bch & (CH - 1);
    const int b = bch >> 4;

    const float A = -__expf(A_log[d * STATE + n]);
    const float Dv = Dp[d];
    float S = 0.f, s = 0.f;

    size_t tok = (size_t)b * SEQ + (size_t)c * CT;

    float dsp = dsp_[tok * INNER + d];
    float xv  = xc[tok * INNER + d];
    float Bv  = bc[tok * 2 * STATE + n];
    float Cv  = bc[tok * 2 * STATE + STATE + n];

    for (int t = 0; t < CT; t++) {
        float dsp_nx = 0.f, x_nx = 0.f, b_nx = 0.f, c_nx = 0.f;
        if (t + 1 < CT) {
            const size_t tk = tok + 1;
            dsp_nx = dsp_[tk * INNER + d];
            x_nx   = xc[tk * INNER + d];
            b_nx   = bc[tk * 2 * STATE + n];
            c_nx   = bc[tk * 2 * STATE + STATE + n];
        }
        S += dsp;
        const float a = __expf(A * dsp);
        s = a * s + dsp * Bv * xv;
        float p = Cv * s;
        p += __shfl_xor_sync(0xffffffffu, p, 8);
        p += __shfl_xor_sync(0xffffffffu, p, 4);
        p += __shfl_xor_sync(0xffffffffu, p, 2);
        p += __shfl_xor_sync(0xffffffffu, p, 1);
        if (n == 0)
            yloc[tok * INNER + d] = p + Dv * xv;
        tok++;
        dsp = dsp_nx; xv = x_nx; Bv = b_nx; Cv = c_nx;
    }

    const size_t o = (size_t)grp * STATE + n;
    pa[o] = __expf(A * S);
    he[o] = s;
}

__global__ void scan_combine_kernel(const float* __restrict__ pa,
                                    const float* __restrict__ he,
                                    float* __restrict__ hin)
{
    const int idx = blockIdx.x * blockDim.x + threadIdx.x;
    if (idx >= BATCH * INNER * STATE) return;
    const int n = idx & 15;
    const int grp = idx >> 4;
    const int d = grp % INNER;
    const int b = grp / INNER;

    float h = 0.f;
    #pragma unroll
    for (int c = 0; c < CH; c++) {
        const size_t o = (((size_t)(b * CH + c) * INNER) + d) * STATE + n;
        hin[o] = h;
        h = pa[o] * h + he[o];
    }
}

// Phase 3 output y feeds out_proj GEMM -> round to tf32.
__global__ void scan_fixup_kernel(const float* __restrict__ dsp_,
                                  const float* __restrict__ bc,
                                  const float* __restrict__ A_log,
                                  const float* __restrict__ hin,
                                  const float* __restrict__ yloc,
                                  const float* __restrict__ xz,
                                  float* __restrict__ y)
{
    const int idx = blockIdx.x * blockDim.x + threadIdx.x;
    const int n = idx & 15;
    const int grp = idx >> 4;
    const int d = grp % INNER;
    const int bch = grp / INNER;
    const int c = bch & (CH - 1);
    const int b = bch >> 4;

    const float A = -__expf(A_log[d * STATE + n]);
    const float h0 = hin[(size_t)grp * STATE + n];
    float S = 0.f;

    size_t tok = (size_t)b * SEQ + (size_t)c * CT;

    float dsp = dsp_[tok * INNER + d];
    float Cv  = bc[tok * 2 * STATE + STATE + n];

    for (int t = 0; t < CT; t++) {
        float dsp_nx = 0.f, c_nx = 0.f;
        if (t + 1 < CT) {
            const size_t tk = tok + 1;
            dsp_nx = dsp_[tk * INNER + d];
            c_nx   = bc[tk * 2 * STATE + STATE + n];
        }
        S += dsp;
        float p = Cv * __expf(A * S) * h0;
        p += __shfl_xor_sync(0xffffffffu, p, 8);
        p += __shfl_xor_sync(0xffffffffu, p, 4);
        p += __shfl_xor_sync(0xffffffffu, p, 2);
        p += __shfl_xor_sync(0xffffffffu, p, 1);
        if (n == 0) {
            const float zv = xz[tok * 2 * INNER + INNER + d];
            const float sz = zv / (1.f + __expf(-zv));
            y[tok * INNER + d] = tf32r((yloc[tok * INNER + d] + p) * sz);
        }
        tok++;
        dsp = dsp_nx; Cv = c_nx;
    }
}

// ---------------------------------------------------------------------------
// Fused: x2 = xres + LN(o); h2 = RMSNorm(x2). h2 rounded (feeds GEMMs),
// x2 exact (residual path to final output).
// ---------------------------------------------------------------------------
__global__ void ln_residual_rms_kernel(const float* __restrict__ o_,
                                       const float* __restrict__ xres,
                                       const float* __restrict__ gamma,
                                       const float* __restrict__ beta,
                                       const float* __restrict__ rms_w,
                                       float* __restrict__ x2,
                                       float* __restrict__ h2)
{
    const int warp = (blockIdx.x * blockDim.x + threadIdx.x) >> 5;
    const int lane = threadIdx.x & 31;
    if (warp >= TOK) return;
    const size_t row = (size_t)warp * DMODEL;

    float o[12];
    float mu = 0.f;
    #pragma unroll
    for (int c = 0; c < 12; c++) {
        o[c] = o_[row + lane + c * 32];
        mu += o[c];
    }
    #pragma unroll
    for (int s = 16; s; s >>= 1) mu += __shfl_xor_sync(0xffffffffu, mu, s);
    mu *= (1.f / DMODEL);

    float var = 0.f;
    #pragma unroll
    for (int c = 0; c < 12; c++) {
        const float dd = o[c] - mu;
        var += dd * dd;
    }
    #pragma unroll
    for (int s = 16; s; s >>= 1) var += __shfl_xor_sync(0xffffffffu, var, s);
    var *= (1.f / DMODEL);
    const float inv = rsqrtf(var + 1e-5f);

    float r[12];
    float ss = 0.f;
    #pragma unroll
    for (int c = 0; c < 12; c++) {
        const int i = lane + c * 32;
        const float v = xres[row + i] + (o[c] - mu) * inv * gamma[i] + beta[i];
        r[c] = v;
        x2[row + i] = v;
        ss += v * v;
    }
    #pragma unroll
    for (int s = 16; s; s >>= 1) ss += __shfl_xor_sync(0xffffffffu, ss, s);
    const float rinv = rsqrtf(ss * (1.f / DMODEL) + 1e-6f);
    #pragma unroll
    for (int c = 0; c < 12; c++) {
        const int i = lane + c * 32;
        h2[row + i] = tf32r(r[c] * rinv * rms_w[i]);
    }
}

// ---------------------------------------------------------------------------
// launch
// ---------------------------------------------------------------------------
static inline float* sym(const void* symbol)
{
    void* p = nullptr;
    cudaGetSymbolAddress(&p, symbol);
    return (float*)p;
}

extern "C" void kernel_launch(void* const* d_in, const int* in_sizes, int n_in,
                              void* d_out, int out_size)
{
    const float* x        = (const float*)d_in[0];
    const float* rms1_w   = (const float*)d_in[1];
    const float* rms2_w   = (const float*)d_in[2];
    const float* in_proj  = (const float*)d_in[3];
    const float* conv_w   = (const float*)d_in[4];
    const float* conv_b   = (const float*)d_in[5];
    const float* x_proj   = (const float*)d_in[6];
    const float* dt_proj  = (const float*)d_in[7];
    const float* dt_b     = (const float*)d_in[8];
    const float* A_log    = (const float*)d_in[9];
    const float* D_param  = (const float*)d_in[10];
    const float* out_proj = (const float*)d_in[11];
    const float* ln_g     = (const float*)d_in[12];
    const float* ln_b     = (const float*)d_in[13];
    const float* gate_w   = (const float*)d_in[14];
    const float* up_w     = (const float*)d_in[15];
    const float* down_w   = (const float*)d_in[16];
    float* out = (float*)d_out;

    float* h    = sym(g_h);
    float* xz   = sym(g_xz);
    float* xs   = sym(g_xs);
    float* xc   = sym(g_xc);
    float* bcp  = sym(g_bc);
    float* dl   = sym(g_dl);
    float* y    = sym(g_y);
    float* o    = sym(g_o);
    float* x2   = sym(g_x2);
    float* h2   = sym(g_h2);
    float* gate = sym(g_gate);
    float* hid  = sym(g_hid);
    float* pa   = sym(g_pa);
    float* he   = sym(g_he);
    float* hin  = sym(g_hin);
    float* wip  = sym(g_wip);
    float* wcv  = sym(g_wcv);
    float* wxp  = sym(g_wxp);
    float* wdt  = sym(g_wdt);
    float* wop  = sym(g_wop);
    float* wgt  = sym(g_wgt);
    float* wup  = sym(g_wup);
    float* wdn  = sym(g_wdn);

    const dim3 tpb(256);

    // 0. pre-round (and pad) weights
    prep_weights_kernel<<<(NTOTW + 255) / 256, tpb>>>(
        in_proj, conv_w, x_proj, dt_proj, out_proj, gate_w, up_w, down_w);

    // 1. h = rmsnorm(x) (rounded)
    rmsnorm_kernel<<<TOK / 8, 256>>>(x, rms1_w, h);

    // 2. xz = h @ in_proj   N=1536 K=384
    mma_gemm_kernel<<<dim3(1536 / BN, TOK / BM), tpb>>>(
        h, wip, xz, TOK, 2 * INNER, DMODEL, 2 * INNER, 0, nullptr, nullptr);

    // 3. im2col shift
    conv_shift_kernel<<<(TOK * KW * INNER / 4 + 255) / 256, tpb>>>(xz, xs);

    // 4. xc = silu(xs @ conv_w + b)   N=768 K=3072
    mma_gemm_kernel<<<dim3(INNER / BN, TOK / BM), tpb>>>(
        xs, wcv, xc, TOK, INNER, KW * INNER, INNER, 1, conv_b, nullptr);

    // 5. bc = xc @ x_proj (padded N=128, logical 32)  K=768
    mma_gemm_kernel<<<dim3(NXPAD / BN, TOK / BM), tpb>>>(
        xc, wxp, bcp, TOK, NXPAD, INNER, 2 * STATE, 0, nullptr, nullptr);

    // 6. dsp = softplus(xc @ dt_proj + dt_b)   N=768 K=768
    mma_gemm_kernel<<<dim3(INNER / BN, TOK / BM), tpb>>>(
        xc, wdt, dl, TOK, INNER, INNER, INNER, 4, dt_b, nullptr);

    // 7. chunked scan + gating
    scan_chunk_kernel<<<(BATCH * CH * INNER * STATE) / 256, tpb>>>(
        xc, dl, bcp, A_log, D_param, y, pa, he);
    scan_combine_kernel<<<(BATCH * INNER * STATE + 255) / 256, tpb>>>(
        pa, he, hin);
    scan_fixup_kernel<<<(BATCH * CH * INNER * STATE) / 256, tpb>>>(
        dl, bcp, A_log, hin, y, xz, y);

    // 8. o = y @ out_proj   N=384 K=768
    mma_gemm_kernel<<<dim3(DMODEL / BN, TOK / BM), tpb>>>(
        y, wop, o, TOK, DMODEL, INNER, DMODEL, 0, nullptr, nullptr);

    // 9. x2 = x + LN(o); h2 = RMSNorm(x2)
    ln_residual_rms_kernel<<<TOK / 8, 256>>>(o, x, ln_g, ln_b, rms2_w, x2, h2);

    // 10. gate = h2 @ gate_w   N=1024 K=384
    mma_gemm_kernel<<<dim3(FFN / BN, TOK / BM), tpb>>>(
        h2, wgt, gate, TOK, FFN, DMODEL, FFN, 0, nullptr, nullptr);
    // 11. hid = silu(gate) * (h2 @ up_w)
    mma_gemm_kernel<<<dim3(FFN / BN, TOK / BM), tpb>>>(
        h2, wup, hid, TOK, FFN, DMODEL, FFN, 5, nullptr, gate);

    // 12. out = x2 + hid @ down_w   N=384 K=1024  (exact, no rounding)
    mma_gemm_kernel<<<dim3(DMODEL / BN, TOK / BM), tpb>>>(
        hid, wdn, out, TOK, DMODEL, FFN, DMODEL, 3, nullptr, x2);
}